// round 10
// baseline (speedup 1.0000x reference)
#include <cuda_runtime.h>

#define NB 4
#define NV 6890
#define NF 13776
#define NS 4096

struct Keys {
    unsigned k1[NB][2];
    unsigned k2[NB][2];
    unsigned k3[NB][2];
};

__device__ float2   g_invw2[NB * NF];        // (wpred, wgt) interleaved
__device__ int      g_fidx[2 * NB * NS];
__device__ float    g_pts [2 * NB * NS * 3];
__device__ float    g_pmin[8 * 4 * NS];      // [seg][qquarter][i]
__device__ double   g_acc;
__device__ int      g_is64;
__device__ unsigned g_one = 1;               // opaque 1: forces IMAD, not IADD3

// ---------------- threefry2x32 (20 rounds), exact JAX semantics ----------------
__host__ __device__ __forceinline__ void tf2x32(unsigned k0, unsigned k1,
                                                unsigned c0, unsigned c1,
                                                unsigned &o0, unsigned &o1)
{
    unsigned ks2 = k0 ^ k1 ^ 0x1BD11BDAu;
    unsigned x0 = c0 + k0;
    unsigned x1 = c1 + k1;
#if defined(__CUDA_ARCH__)
#define TF_ROTL(x, r) __funnelshift_l((x), (x), (r))
#else
#define TF_ROTL(x, r) (((x) << (r)) | ((x) >> (32 - (r))))
#endif
#define TF_RND(r) { x0 += x1; x1 = TF_ROTL(x1, r); x1 ^= x0; }
    TF_RND(13) TF_RND(15) TF_RND(26) TF_RND(6)
    x0 += k1;  x1 += ks2 + 1u;
    TF_RND(17) TF_RND(29) TF_RND(16) TF_RND(24)
    x0 += ks2; x1 += k0 + 2u;
    TF_RND(13) TF_RND(15) TF_RND(26) TF_RND(6)
    x0 += k0;  x1 += k1 + 3u;
    TF_RND(17) TF_RND(29) TF_RND(16) TF_RND(24)
    x0 += k1;  x1 += ks2 + 4u;
    TF_RND(13) TF_RND(15) TF_RND(26) TF_RND(6)
    x0 += ks2; x1 += k0 + 5u;
#undef TF_RND
#undef TF_ROTL
    o0 = x0; o1 = x1;
}

// partitionable random_bits (32-bit): counter = (0, flat_index), out = x0 ^ x1
__host__ __device__ __forceinline__ unsigned tf_bits(unsigned k0, unsigned k1,
                                                     unsigned e)
{
    unsigned o0, o1;
    tf2x32(k0, k1, 0u, e, o0, o1);
    return o0 ^ o1;
}

// Pipe-balanced threefry for c0=0: integer adds forced onto the fma pipe as
// IMAD (mad.lo with opaque one); SHF/LOP3 stay on the alu pipe.
// Caller passes cnt = e + k1 (pre-added).
#define MADD(d, a) asm("mad.lo.u32 %0, %1, %2, %0;" : "+r"(d) : "r"(a), "r"(one))

__device__ __forceinline__ unsigned tf_fast(unsigned k0, unsigned k1, unsigned ks2,
                                            unsigned B1, unsigned B2, unsigned B3,
                                            unsigned B4, unsigned B5,
                                            unsigned cnt, unsigned one)
{
    unsigned x0 = k0;        // 0 + k0
    unsigned x1 = cnt;       // e + k1 (pre-added by caller)
#define TFR(r) { MADD(x0, x1); x1 = __funnelshift_l(x1, x1, r) ^ x0; }
    TFR(13) TFR(15) TFR(26) TFR(6)
    MADD(x0, k1);  MADD(x1, B1);
    TFR(17) TFR(29) TFR(16) TFR(24)
    MADD(x0, ks2); MADD(x1, B2);
    TFR(13) TFR(15) TFR(26) TFR(6)
    MADD(x0, k0);  MADD(x1, B3);
    TFR(17) TFR(29) TFR(16) TFR(24)
    MADD(x0, k1);  MADD(x1, B4);
    TFR(13) TFR(15) TFR(26) TFR(6)
    MADD(x0, ks2); MADD(x1, B5);
#undef TFR
    return x0 ^ x1;
}

// -------- accurate -log(u'), u' = (m==0 ? tiny : m*2^-23), ~1-2 ulp relative ----
__device__ __forceinline__ float neglog_u(unsigned m)  // m = bits >> 9
{
    float u;
    if (m == 0u) u = 1.17549435e-38f;                         // finfo(f32).tiny
    else         u = __uint_as_float(0x3f800000u | m) - 1.0f; // exact
    unsigned bi = __float_as_uint(u);
    int e = (int)(bi >> 23) - 126;                            // u = x0*2^e, x0 in [0.5,1)
    float x = __uint_as_float((bi & 0x007fffffu) | (126u << 23));
    if (x < 0.70710678f) { x = x + x; e -= 1; }               // x in [0.7071, 1.4142)
    float s = __fdiv_rn(x - 1.0f, x + 1.0f);                  // x-1 exact (Sterbenz)
    float t = s * s;
    float P = __fmaf_rn(t, __fmaf_rn(t, __fmaf_rn(t, 0.11111111f, 0.14285715f),
                                     0.2f), 0.33333334f);
    float q = s + s;
    float lnx = __fmaf_rn(q * t, P, q);                       // ln x = 2s + 2s*t*P
    float kf = (float)e;
    float r = __fmaf_rn(kf, -2.12194440e-4f, lnx);            // ln2_lo
    r = __fmaf_rn(kf, 0.693359375f, r);                       // ln2_hi
    return -r;
}

// ---------------- tf32 rounding (RNA, matches cvt.rna.tf32.f32) ----------------
__device__ __forceinline__ float tf32r(float x)
{
    unsigned b = __float_as_uint(x);
    b = (b + 0x1000u) & 0xffffe000u;
    return __uint_as_float(b);
}

// ---------------- faces dtype detection (int32 vs int64) ----------------
__global__ void k_detect(const int* __restrict__ pf32)
{
    if (threadIdx.x == 0) {
        int is64 = 1;
        for (int i = 0; i < 64; i++)
            if (pf32[2 * i + 1] != 0) { is64 = 0; break; }
        g_is64 = is64;
    }
}

__device__ __forceinline__ void load_face(const void* faces, long long fe,
                                          int &i0, int &i1, int &i2, int is64)
{
    if (is64) {
        const long long* p = (const long long*)faces + fe * 3;
        i0 = (int)p[0]; i1 = (int)p[1]; i2 = (int)p[2];
    } else {
        const int* p = (const int*)faces + fe * 3;
        i0 = p[0]; i1 = p[1]; i2 = p[2];
    }
}

// ---------------- per-face inverse (area + 1e-12) ----------------
__global__ void k_area(const float* __restrict__ pv, const void* __restrict__ pf,
                       const float* __restrict__ gv, const void* __restrict__ gf)
{
    int t = blockIdx.x * blockDim.x + threadIdx.x;
    if (t >= 2 * NB * NF) return;
    int is64 = g_is64;
    int type = t / (NB * NF);
    int rem  = t - type * (NB * NF);
    int b = rem / NF, f = rem - b * NF;
    const float* verts = (type ? gv : pv) + (size_t)b * NV * 3;
    int i0, i1, i2;
    load_face(type ? gf : pf, (long long)b * NF + f, i0, i1, i2, is64);
    float v0x = verts[i0*3+0], v0y = verts[i0*3+1], v0z = verts[i0*3+2];
    float ax = verts[i1*3+0] - v0x, ay = verts[i1*3+1] - v0y, az = verts[i1*3+2] - v0z;
    float bx = verts[i2*3+0] - v0x, by = verts[i2*3+1] - v0y, bz = verts[i2*3+2] - v0z;
    float cx = ay * bz - az * by;
    float cy = az * bx - ax * bz;
    float cz = ax * by - ay * bx;
    float cn = __fsqrt_rn(cx * cx + cy * cy + cz * cz);
    ((float*)g_invw2)[(b * NF + f) * 2 + type] = __fdiv_rn(1.0f, 0.5f * cn + 1e-12f);
}

// ---------------- gumbel-argmin (categorical), warp-per-row, ILP-4 ----------------
// Prefilter with cheap lower bounds (rn((1-u)w) <= rn(-lnu*w), rn monotone)
// against pre-group bests (superset of per-candidate tests); exact sequential
// compares inside decide. Bit-identical to evaluating every candidate.
__global__ void __launch_bounds__(128, 12) k_argmin(Keys keys)
{
    unsigned one = g_one;
    int gw   = blockIdx.x * 4 + (threadIdx.x >> 5);  // global warp = row id
    int lane = threadIdx.x & 31;
    int b = gw >> 12;                                // 4096 rows per batch
    int i = gw & (NS - 1);
    unsigned k0 = keys.k1[b][0], k1 = keys.k1[b][1];
    unsigned ks2 = k0 ^ k1 ^ 0x1BD11BDAu;
    unsigned B1 = ks2 + 1u, B2 = k0 + 2u, B3 = k1 + 3u, B4 = ks2 + 4u, B5 = k0 + 5u;
    const float2* __restrict__ w2 = g_invw2 + b * NF;
    float bb0f = 3.402823466e38f, bb1f = 3.402823466e38f;
    int bf0 = NF, bf1 = NF;
    unsigned eoff = (unsigned)i * (unsigned)NF + k1;

    int f1 = lane;
    unsigned cnt1 = eoff + (unsigned)lane;

    // main: 107 iterations x 4 chains (107*128 = 13696)
    for (int t = 0; t < 107; t++) {
        unsigned bits0 = tf_fast(k0, k1, ks2, B1, B2, B3, B4, B5, cnt1,       one);
        unsigned bits1 = tf_fast(k0, k1, ks2, B1, B2, B3, B4, B5, cnt1 + 32u, one);
        unsigned bits2 = tf_fast(k0, k1, ks2, B1, B2, B3, B4, B5, cnt1 + 64u, one);
        unsigned bits3 = tf_fast(k0, k1, ks2, B1, B2, B3, B4, B5, cnt1 + 96u, one);
        float2 w0 = __ldg(w2 + f1);
        float2 w1 = __ldg(w2 + f1 + 32);
        float2 wv2 = __ldg(w2 + f1 + 64);
        float2 w3 = __ldg(w2 + f1 + 96);
        // m = bits >> 9 via umulhi (fma pipe); v-bits OR on alu (1 LOP3 each)
        unsigned m0 = __umulhi(bits0, 0x800000u);
        unsigned m1 = __umulhi(bits1, 0x800000u);
        unsigned m2 = __umulhi(bits2, 0x800000u);
        unsigned m3 = __umulhi(bits3, 0x800000u);
        float yl0 = 2.0f - __uint_as_float(0x3f800000u | m0);  // 1-u, exact
        float yl1 = 2.0f - __uint_as_float(0x3f800000u | m1);
        float yl2 = 2.0f - __uint_as_float(0x3f800000u | m2);
        float yl3 = 2.0f - __uint_as_float(0x3f800000u | m3);
        float c00 = __fmul_rn(yl0, w0.x),  c10 = __fmul_rn(yl0, w0.y);
        float c01 = __fmul_rn(yl1, w1.x),  c11 = __fmul_rn(yl1, w1.y);
        float c02 = __fmul_rn(yl2, wv2.x), c12 = __fmul_rn(yl2, wv2.y);
        float c03 = __fmul_rn(yl3, w3.x),  c13 = __fmul_rn(yl3, w3.y);
        int hit = (c00 < bb0f) | (c01 < bb0f) | (c02 < bb0f) | (c03 < bb0f)
                | (c10 < bb1f) | (c11 < bb1f) | (c12 < bb1f) | (c13 < bb1f);
        if (hit) {
            float lg0 = neglog_u(m0), lg1 = neglog_u(m1);
            float lg2 = neglog_u(m2), lg3 = neglog_u(m3);
            float t0;
            t0 = __fmul_rn(lg0, w0.x);  if (t0 < bb0f) { bb0f = t0; bf0 = f1; }
            t0 = __fmul_rn(lg0, w0.y);  if (t0 < bb1f) { bb1f = t0; bf1 = f1; }
            t0 = __fmul_rn(lg1, w1.x);  if (t0 < bb0f) { bb0f = t0; bf0 = f1 + 32; }
            t0 = __fmul_rn(lg1, w1.y);  if (t0 < bb1f) { bb1f = t0; bf1 = f1 + 32; }
            t0 = __fmul_rn(lg2, wv2.x); if (t0 < bb0f) { bb0f = t0; bf0 = f1 + 64; }
            t0 = __fmul_rn(lg2, wv2.y); if (t0 < bb1f) { bb1f = t0; bf1 = f1 + 64; }
            t0 = __fmul_rn(lg3, w3.x);  if (t0 < bb0f) { bb0f = t0; bf0 = f1 + 96; }
            t0 = __fmul_rn(lg3, w3.y);  if (t0 < bb1f) { bb1f = t0; bf1 = f1 + 96; }
        }
        f1 += 128;
        MADD(cnt1, 128u);
    }
    {   // 2-chain step: f in [13696, 13760)
        unsigned bits0 = tf_fast(k0, k1, ks2, B1, B2, B3, B4, B5, cnt1,       one);
        unsigned bits1 = tf_fast(k0, k1, ks2, B1, B2, B3, B4, B5, cnt1 + 32u, one);
        float2 w0 = __ldg(w2 + f1);
        float2 w1 = __ldg(w2 + f1 + 32);
        unsigned m0 = __umulhi(bits0, 0x800000u);
        unsigned m1 = __umulhi(bits1, 0x800000u);
        float yl0 = 2.0f - __uint_as_float(0x3f800000u | m0);
        float yl1 = 2.0f - __uint_as_float(0x3f800000u | m1);
        float c00 = __fmul_rn(yl0, w0.x), c10 = __fmul_rn(yl0, w0.y);
        float c01 = __fmul_rn(yl1, w1.x), c11 = __fmul_rn(yl1, w1.y);
        int hit = (c00 < bb0f) | (c01 < bb0f) | (c10 < bb1f) | (c11 < bb1f);
        if (hit) {
            float lg0 = neglog_u(m0), lg1 = neglog_u(m1);
            float t0;
            t0 = __fmul_rn(lg0, w0.x); if (t0 < bb0f) { bb0f = t0; bf0 = f1; }
            t0 = __fmul_rn(lg0, w0.y); if (t0 < bb1f) { bb1f = t0; bf1 = f1; }
            t0 = __fmul_rn(lg1, w1.x); if (t0 < bb0f) { bb0f = t0; bf0 = f1 + 32; }
            t0 = __fmul_rn(lg1, w1.y); if (t0 < bb1f) { bb1f = t0; bf1 = f1 + 32; }
        }
        f1 += 64;
        MADD(cnt1, 64u);
    }
    if (lane < 16) {                                  // f in [13760, 13776)
        unsigned bits = tf_fast(k0, k1, ks2, B1, B2, B3, B4, B5, cnt1, one);
        float2 wt = __ldg(w2 + f1);
        unsigned m = __umulhi(bits, 0x800000u);
        float yl = 2.0f - __uint_as_float(0x3f800000u | m);
        float c0 = __fmul_rn(yl, wt.x), c1 = __fmul_rn(yl, wt.y);
        if ((c0 < bb0f) | (c1 < bb1f)) {
            float lg = neglog_u(m);
            float t0 = __fmul_rn(lg, wt.x);
            if (t0 < bb0f) { bb0f = t0; bf0 = f1; }
            float t1 = __fmul_rn(lg, wt.y);
            if (t1 < bb1f) { bb1f = t1; bf1 = f1; }
        }
    }

#pragma unroll
    for (int off = 16; off > 0; off >>= 1) {
        float ob; int of;
        ob = __shfl_down_sync(0xffffffffu, bb0f, off);
        of = __shfl_down_sync(0xffffffffu, bf0, off);
        if (ob < bb0f || (ob == bb0f && of < bf0)) { bb0f = ob; bf0 = of; }
        ob = __shfl_down_sync(0xffffffffu, bb1f, off);
        of = __shfl_down_sync(0xffffffffu, bf1, off);
        if (ob < bb1f || (ob == bb1f && of < bf1)) { bb1f = ob; bf1 = of; }
    }
    if (lane == 0) {
        g_fidx[(0 * NB + b) * NS + i] = bf0;
        g_fidx[(1 * NB + b) * NS + i] = bf1;
    }
}

// ---------------- barycentric point generation ----------------
__global__ void k_points(Keys keys,
                         const float* __restrict__ pv, const void* __restrict__ pf,
                         const float* __restrict__ gv, const void* __restrict__ gf)
{
    int t = blockIdx.x * blockDim.x + threadIdx.x;
    if (t >= NB * NS) return;
    int is64 = g_is64;
    int b = t >> 12, i = t & (NS - 1);
    unsigned bu = tf_bits(keys.k2[b][0], keys.k2[b][1], (unsigned)i);
    unsigned bw = tf_bits(keys.k3[b][0], keys.k3[b][1], (unsigned)i);
    float u = __uint_as_float(0x3f800000u | (bu >> 9)) - 1.0f;
    float w = __uint_as_float(0x3f800000u | (bw >> 9)) - 1.0f;
    float r = __fsqrt_rn(u);
    float a0 = 1.0f - r;
    float a1 = __fmul_rn(r, 1.0f - w);
    float a2 = __fmul_rn(r, w);
    for (int type = 0; type < 2; type++) {
        const float* verts = (type ? gv : pv) + (size_t)b * NV * 3;
        int f = g_fidx[(type * NB + b) * NS + i];
        int i0, i1, i2;
        load_face(type ? gf : pf, (long long)b * NF + f, i0, i1, i2, is64);
        float* dst = g_pts + ((size_t)(type * NB + b) * NS + i) * 3;
#pragma unroll
        for (int c = 0; c < 3; c++)
            dst[c] = a0 * verts[i0*3+c] + a1 * verts[i1*3+c] + a2 * verts[i2*3+c];
    }
}

// ---------------- brute-force two-way chamfer, TF32-emulated dot ----------------
__global__ void __launch_bounds__(256) k_chamfer()
{
    int blk   = blockIdx.x;        // 128
    int itile = blk & 3;
    int qq    = (blk >> 2) & 3;
    int seg   = blk >> 4;          // 0..7 : b*2 + dir
    int b = seg >> 1, dir = seg & 1;
    const float* __restrict__ A  = g_pts + (size_t)((dir ? NB : 0) + b) * NS * 3;
    const float* __restrict__ Bq = g_pts + (size_t)((dir ? 0 : NB) + b) * NS * 3;
    int tid = threadIdx.x;

    float tpx[4], tpy[4], tpz[4], ppv[4], mind[4];
#pragma unroll
    for (int r = 0; r < 4; r++) {
        int i = itile * 1024 + r * 256 + tid;
        float px = A[i*3+0], py = A[i*3+1], pz = A[i*3+2];
        ppv[r] = px*px + py*py + pz*pz;              // exact f32 (outside GEMM)
        tpx[r] = tf32r(px); tpy[r] = tf32r(py); tpz[r] = tf32r(pz);
        mind[r] = 3.4e38f;
    }

    __shared__ float4 sq[256];
    int qbase = qq * 1024;
    for (int qt = 0; qt < 4; qt++) {
        int j = qbase + qt * 256 + tid;
        float qx = Bq[j*3+0], qy = Bq[j*3+1], qz = Bq[j*3+2];
        sq[tid] = make_float4(tf32r(qx), tf32r(qy), tf32r(qz),
                              qx*qx + qy*qy + qz*qz);
        __syncthreads();
#pragma unroll 4
        for (int k = 0; k < 256; k++) {
            float4 q = sq[k];
#pragma unroll
            for (int r = 0; r < 4; r++) {
                float dot = __fmul_rn(q.x, tpx[r]);
                dot = __fmaf_rn(q.y, tpy[r], dot);
                dot = __fmaf_rn(q.z, tpz[r], dot);
                float d = __fmaf_rn(-2.0f, dot, ppv[r] + q.w);
                mind[r] = fminf(mind[r], d);
            }
        }
        __syncthreads();
    }
#pragma unroll
    for (int r = 0; r < 4; r++) {
        int i = itile * 1024 + r * 256 + tid;
        g_pmin[(seg * 4 + qq) * NS + i] = mind[r];
    }
}

__global__ void __launch_bounds__(256) k_combine()
{
    int t = blockIdx.x * 256 + threadIdx.x;   // 0..32767
    int seg = t >> 12, i = t & (NS - 1);
    const float* pm = g_pmin + seg * 4 * NS + i;
    float m = fminf(fminf(pm[0], pm[NS]), fminf(pm[2 * NS], pm[3 * NS]));
    __shared__ double sd[256];
    sd[threadIdx.x] = (double)m;
    __syncthreads();
    for (int off = 128; off > 0; off >>= 1) {
        if (threadIdx.x < off) sd[threadIdx.x] += sd[threadIdx.x + off];
        __syncthreads();
    }
    if (threadIdx.x == 0) atomicAdd(&g_acc, sd[0]);
}

__global__ void k_zero() { g_acc = 0.0; }

__global__ void k_final(float* out)
{
    out[0] = (float)(g_acc * (1.0 / 16384.0));   // mean(d1)+mean(d2), CHAMFER_W=1
}

// ---------------- launch ----------------
extern "C" void kernel_launch(void* const* d_in, const int* in_sizes, int n_in,
                              void* d_out, int out_size)
{
    const float* pv = (const float*)d_in[0];
    const void*  pf = (const void*)d_in[1];
    const float* gv = (const float*)d_in[2];
    const void*  gf = (const void*)d_in[3];

    // Partitionable (foldlike) split: key_i = threefry(key, (0, i)), both
    // outputs form the new key. key(42) = (0, 42).
    Keys keys;
    for (int b = 0; b < 4; b++) {
        unsigned kb0, kb1;
        tf2x32(0u, 42u, 0u, (unsigned)b, kb0, kb1);
        tf2x32(kb0, kb1, 0u, 0u, keys.k1[b][0], keys.k1[b][1]);
        tf2x32(kb0, kb1, 0u, 1u, keys.k2[b][0], keys.k2[b][1]);
        tf2x32(kb0, kb1, 0u, 2u, keys.k3[b][0], keys.k3[b][1]);
    }

    k_detect<<<1, 32>>>((const int*)pf);
    k_zero<<<1, 1>>>();
    k_area<<<(2 * NB * NF + 255) / 256, 256>>>(pv, pf, gv, gf);
    k_argmin<<<NB * NS / 4, 128>>>(keys);
    k_points<<<(NB * NS + 63) / 64, 64>>>(keys, pv, pf, gv, gf);
    k_chamfer<<<128, 256>>>();
    k_combine<<<128, 256>>>();
    k_final<<<1, 1>>>((float*)d_out);
}

// round 11
// speedup vs baseline: 1.0460x; 1.0460x over previous
#include <cuda_runtime.h>

#define NB 4
#define NV 6890
#define NF 13776
#define NS 4096

struct Keys {
    unsigned k1[NB][2];
    unsigned k2[NB][2];
    unsigned k3[NB][2];
};

__device__ float2   g_invw2[NB * NF];        // (wpred, wgt) interleaved
__device__ int      g_fidx[2 * NB * NS];
__device__ float    g_pts [2 * NB * NS * 3];
__device__ float    g_pmin[8 * 4 * NS];      // [seg][qquarter][i]
__device__ double   g_acc;
__device__ int      g_is64;
__device__ unsigned g_one = 1;               // opaque 1: forces IMAD, not IADD3

// ---------------- threefry2x32 (20 rounds), exact JAX semantics ----------------
__host__ __device__ __forceinline__ void tf2x32(unsigned k0, unsigned k1,
                                                unsigned c0, unsigned c1,
                                                unsigned &o0, unsigned &o1)
{
    unsigned ks2 = k0 ^ k1 ^ 0x1BD11BDAu;
    unsigned x0 = c0 + k0;
    unsigned x1 = c1 + k1;
#if defined(__CUDA_ARCH__)
#define TF_ROTL(x, r) __funnelshift_l((x), (x), (r))
#else
#define TF_ROTL(x, r) (((x) << (r)) | ((x) >> (32 - (r))))
#endif
#define TF_RND(r) { x0 += x1; x1 = TF_ROTL(x1, r); x1 ^= x0; }
    TF_RND(13) TF_RND(15) TF_RND(26) TF_RND(6)
    x0 += k1;  x1 += ks2 + 1u;
    TF_RND(17) TF_RND(29) TF_RND(16) TF_RND(24)
    x0 += ks2; x1 += k0 + 2u;
    TF_RND(13) TF_RND(15) TF_RND(26) TF_RND(6)
    x0 += k0;  x1 += k1 + 3u;
    TF_RND(17) TF_RND(29) TF_RND(16) TF_RND(24)
    x0 += k1;  x1 += ks2 + 4u;
    TF_RND(13) TF_RND(15) TF_RND(26) TF_RND(6)
    x0 += ks2; x1 += k0 + 5u;
#undef TF_RND
#undef TF_ROTL
    o0 = x0; o1 = x1;
}

// partitionable random_bits (32-bit): counter = (0, flat_index), out = x0 ^ x1
__host__ __device__ __forceinline__ unsigned tf_bits(unsigned k0, unsigned k1,
                                                     unsigned e)
{
    unsigned o0, o1;
    tf2x32(k0, k1, 0u, e, o0, o1);
    return o0 ^ o1;
}

// Pipe-balanced threefry for c0=0: integer adds forced onto the fma pipe as
// IMAD (mad.lo with opaque one); SHF/LOP3 stay on the alu pipe.
// Caller passes cnt = e + k1 (pre-added).
#define MADD(d, a) asm("mad.lo.u32 %0, %1, %2, %0;" : "+r"(d) : "r"(a), "r"(one))

__device__ __forceinline__ unsigned tf_fast(unsigned k0, unsigned k1, unsigned ks2,
                                            unsigned B1, unsigned B2, unsigned B3,
                                            unsigned B4, unsigned B5,
                                            unsigned cnt, unsigned one)
{
    unsigned x0 = k0;        // 0 + k0
    unsigned x1 = cnt;       // e + k1 (pre-added by caller)
#define TFR(r) { MADD(x0, x1); x1 = __funnelshift_l(x1, x1, r) ^ x0; }
    TFR(13) TFR(15) TFR(26) TFR(6)
    MADD(x0, k1);  MADD(x1, B1);
    TFR(17) TFR(29) TFR(16) TFR(24)
    MADD(x0, ks2); MADD(x1, B2);
    TFR(13) TFR(15) TFR(26) TFR(6)
    MADD(x0, k0);  MADD(x1, B3);
    TFR(17) TFR(29) TFR(16) TFR(24)
    MADD(x0, k1);  MADD(x1, B4);
    TFR(13) TFR(15) TFR(26) TFR(6)
    MADD(x0, ks2); MADD(x1, B5);
#undef TFR
    return x0 ^ x1;
}

// -------- accurate -log(u'), u' = (m==0 ? tiny : m*2^-23), ~1-2 ulp relative ----
__device__ __forceinline__ float neglog_u(unsigned m)  // m = bits >> 9
{
    float u;
    if (m == 0u) u = 1.17549435e-38f;                         // finfo(f32).tiny
    else         u = __uint_as_float(0x3f800000u | m) - 1.0f; // exact
    unsigned bi = __float_as_uint(u);
    int e = (int)(bi >> 23) - 126;                            // u = x0*2^e, x0 in [0.5,1)
    float x = __uint_as_float((bi & 0x007fffffu) | (126u << 23));
    if (x < 0.70710678f) { x = x + x; e -= 1; }               // x in [0.7071, 1.4142)
    float s = __fdiv_rn(x - 1.0f, x + 1.0f);                  // x-1 exact (Sterbenz)
    float t = s * s;
    float P = __fmaf_rn(t, __fmaf_rn(t, __fmaf_rn(t, 0.11111111f, 0.14285715f),
                                     0.2f), 0.33333334f);
    float q = s + s;
    float lnx = __fmaf_rn(q * t, P, q);                       // ln x = 2s + 2s*t*P
    float kf = (float)e;
    float r = __fmaf_rn(kf, -2.12194440e-4f, lnx);            // ln2_lo
    r = __fmaf_rn(kf, 0.693359375f, r);                       // ln2_hi
    return -r;
}

// ---------------- tf32 rounding (RNA, matches cvt.rna.tf32.f32) ----------------
__device__ __forceinline__ float tf32r(float x)
{
    unsigned b = __float_as_uint(x);
    b = (b + 0x1000u) & 0xffffe000u;
    return __uint_as_float(b);
}

// ---------------- faces dtype detection (int32 vs int64) + zero ----------------
__global__ void k_detect(const int* __restrict__ pf32)
{
    if (threadIdx.x == 0) {
        int is64 = 1;
        for (int i = 0; i < 64; i++)
            if (pf32[2 * i + 1] != 0) { is64 = 0; break; }
        g_is64 = is64;
        g_acc = 0.0;
    }
}

__device__ __forceinline__ void load_face(const void* faces, long long fe,
                                          int &i0, int &i1, int &i2, int is64)
{
    if (is64) {
        const long long* p = (const long long*)faces + fe * 3;
        i0 = (int)p[0]; i1 = (int)p[1]; i2 = (int)p[2];
    } else {
        const int* p = (const int*)faces + fe * 3;
        i0 = p[0]; i1 = p[1]; i2 = p[2];
    }
}

// ---------------- per-face inverse (area + 1e-12) ----------------
__global__ void k_area(const float* __restrict__ pv, const void* __restrict__ pf,
                       const float* __restrict__ gv, const void* __restrict__ gf)
{
    int t = blockIdx.x * blockDim.x + threadIdx.x;
    if (t >= 2 * NB * NF) return;
    int is64 = g_is64;
    int type = t / (NB * NF);
    int rem  = t - type * (NB * NF);
    int b = rem / NF, f = rem - b * NF;
    const float* verts = (type ? gv : pv) + (size_t)b * NV * 3;
    int i0, i1, i2;
    load_face(type ? gf : pf, (long long)b * NF + f, i0, i1, i2, is64);
    float v0x = verts[i0*3+0], v0y = verts[i0*3+1], v0z = verts[i0*3+2];
    float ax = verts[i1*3+0] - v0x, ay = verts[i1*3+1] - v0y, az = verts[i1*3+2] - v0z;
    float bx = verts[i2*3+0] - v0x, by = verts[i2*3+1] - v0y, bz = verts[i2*3+2] - v0z;
    float cx = ay * bz - az * by;
    float cy = az * bx - ax * bz;
    float cz = ax * by - ay * bx;
    float cn = __fsqrt_rn(cx * cx + cy * cy + cz * cz);
    ((float*)g_invw2)[(b * NF + f) * 2 + type] = __fdiv_rn(1.0f, 0.5f * cn + 1e-12f);
}

// ---------------- gumbel-argmin (categorical), warp-per-row, ILP-2 x2 ----------------
// Prefilter with cheap lower bounds (rn((1-u)w) <= rn(-lnu*w), rn monotone)
// against pre-group bests (superset of per-candidate tests); exact sequential
// compares inside decide. Bit-identical to evaluating every candidate.
#define GROUP2(fb) {                                                            \
    unsigned bits1 = tf_fast(k0, k1, ks2, B1, B2, B3, B4, B5, cnt1,       one); \
    unsigned bits2 = tf_fast(k0, k1, ks2, B1, B2, B3, B4, B5, cnt1 + 32u, one); \
    float2 wa = __ldg(w2 + (fb));                                               \
    float2 wb = __ldg(w2 + (fb) + 32);                                          \
    unsigned m1 = __umulhi(bits1, 0x800000u);   /* bits >> 9, fma pipe */       \
    unsigned m2 = __umulhi(bits2, 0x800000u);                                   \
    float yl1 = 2.0f - __uint_as_float(0x3f800000u | m1);  /* 1-u, exact */     \
    float yl2 = 2.0f - __uint_as_float(0x3f800000u | m2);                       \
    float c0a = __fmul_rn(yl1, wa.x), c1a = __fmul_rn(yl1, wa.y);               \
    float c0b = __fmul_rn(yl2, wb.x), c1b = __fmul_rn(yl2, wb.y);               \
    if (fminf(c0a, c0b) < bb0f || fminf(c1a, c1b) < bb1f) {                     \
        float lg1 = neglog_u(m1);                                               \
        float lg2 = neglog_u(m2);                                               \
        float t0 = __fmul_rn(lg1, wa.x);                                        \
        if (t0 < bb0f) { bb0f = t0; bf0 = (fb); }                               \
        float t1 = __fmul_rn(lg1, wa.y);                                        \
        if (t1 < bb1f) { bb1f = t1; bf1 = (fb); }                               \
        float t2 = __fmul_rn(lg2, wb.x);                                        \
        if (t2 < bb0f) { bb0f = t2; bf0 = (fb) + 32; }                          \
        float t3 = __fmul_rn(lg2, wb.y);                                        \
        if (t3 < bb1f) { bb1f = t3; bf1 = (fb) + 32; }                          \
    }                                                                           \
    MADD(cnt1, 64u); }

__global__ void __launch_bounds__(128, 14) k_argmin(Keys keys)
{
    unsigned one = g_one;
    int gw   = blockIdx.x * 4 + (threadIdx.x >> 5);  // global warp = row id
    int lane = threadIdx.x & 31;
    int b = gw >> 12;                                // 4096 rows per batch
    int i = gw & (NS - 1);
    unsigned k0 = keys.k1[b][0], k1 = keys.k1[b][1];
    unsigned ks2 = k0 ^ k1 ^ 0x1BD11BDAu;
    unsigned B1 = ks2 + 1u, B2 = k0 + 2u, B3 = k1 + 3u, B4 = ks2 + 4u, B5 = k0 + 5u;
    const float2* __restrict__ w2 = g_invw2 + b * NF;
    float bb0f = 3.402823466e38f, bb1f = 3.402823466e38f;
    int bf0 = NF, bf1 = NF;
    unsigned eoff = (unsigned)i * (unsigned)NF + k1;

    int f1 = lane;
    unsigned cnt1 = eoff + (unsigned)lane;

    // main: 107 iterations x (2 sequential ILP-2 groups) = 13696 faces
    for (int t = 0; t < 107; t++) {
        GROUP2(f1)
        GROUP2(f1 + 64)
        f1 += 128;
    }
    GROUP2(f1)                                        // f in [13696, 13760)
    f1 += 64;
    if (lane < 16) {                                  // f in [13760, 13776)
        unsigned bits = tf_fast(k0, k1, ks2, B1, B2, B3, B4, B5, cnt1, one);
        float2 wt = __ldg(w2 + f1);
        unsigned m = __umulhi(bits, 0x800000u);
        float yl = 2.0f - __uint_as_float(0x3f800000u | m);
        float c0 = __fmul_rn(yl, wt.x), c1 = __fmul_rn(yl, wt.y);
        if (c0 < bb0f || c1 < bb1f) {
            float lg = neglog_u(m);
            float t0 = __fmul_rn(lg, wt.x);
            if (t0 < bb0f) { bb0f = t0; bf0 = f1; }
            float t1 = __fmul_rn(lg, wt.y);
            if (t1 < bb1f) { bb1f = t1; bf1 = f1; }
        }
    }

#pragma unroll
    for (int off = 16; off > 0; off >>= 1) {
        float ob; int of;
        ob = __shfl_down_sync(0xffffffffu, bb0f, off);
        of = __shfl_down_sync(0xffffffffu, bf0, off);
        if (ob < bb0f || (ob == bb0f && of < bf0)) { bb0f = ob; bf0 = of; }
        ob = __shfl_down_sync(0xffffffffu, bb1f, off);
        of = __shfl_down_sync(0xffffffffu, bf1, off);
        if (ob < bb1f || (ob == bb1f && of < bf1)) { bb1f = ob; bf1 = of; }
    }
    if (lane == 0) {
        g_fidx[(0 * NB + b) * NS + i] = bf0;
        g_fidx[(1 * NB + b) * NS + i] = bf1;
    }
}

// ---------------- barycentric point generation ----------------
__global__ void k_points(Keys keys,
                         const float* __restrict__ pv, const void* __restrict__ pf,
                         const float* __restrict__ gv, const void* __restrict__ gf)
{
    int t = blockIdx.x * blockDim.x + threadIdx.x;
    if (t >= NB * NS) return;
    int is64 = g_is64;
    int b = t >> 12, i = t & (NS - 1);
    unsigned bu = tf_bits(keys.k2[b][0], keys.k2[b][1], (unsigned)i);
    unsigned bw = tf_bits(keys.k3[b][0], keys.k3[b][1], (unsigned)i);
    float u = __uint_as_float(0x3f800000u | (bu >> 9)) - 1.0f;
    float w = __uint_as_float(0x3f800000u | (bw >> 9)) - 1.0f;
    float r = __fsqrt_rn(u);
    float a0 = 1.0f - r;
    float a1 = __fmul_rn(r, 1.0f - w);
    float a2 = __fmul_rn(r, w);
    for (int type = 0; type < 2; type++) {
        const float* verts = (type ? gv : pv) + (size_t)b * NV * 3;
        int f = g_fidx[(type * NB + b) * NS + i];
        int i0, i1, i2;
        load_face(type ? gf : pf, (long long)b * NF + f, i0, i1, i2, is64);
        float* dst = g_pts + ((size_t)(type * NB + b) * NS + i) * 3;
#pragma unroll
        for (int c = 0; c < 3; c++)
            dst[c] = a0 * verts[i0*3+c] + a1 * verts[i1*3+c] + a2 * verts[i2*3+c];
    }
}

// ---------------- brute-force two-way chamfer, TF32-emulated dot ----------------
__global__ void __launch_bounds__(256) k_chamfer()
{
    int blk   = blockIdx.x;        // 128
    int itile = blk & 3;
    int qq    = (blk >> 2) & 3;
    int seg   = blk >> 4;          // 0..7 : b*2 + dir
    int b = seg >> 1, dir = seg & 1;
    const float* __restrict__ A  = g_pts + (size_t)((dir ? NB : 0) + b) * NS * 3;
    const float* __restrict__ Bq = g_pts + (size_t)((dir ? 0 : NB) + b) * NS * 3;
    int tid = threadIdx.x;

    float tpx[4], tpy[4], tpz[4], ppv[4], mind[4];
#pragma unroll
    for (int r = 0; r < 4; r++) {
        int i = itile * 1024 + r * 256 + tid;
        float px = A[i*3+0], py = A[i*3+1], pz = A[i*3+2];
        ppv[r] = px*px + py*py + pz*pz;              // exact f32 (outside GEMM)
        tpx[r] = tf32r(px); tpy[r] = tf32r(py); tpz[r] = tf32r(pz);
        mind[r] = 3.4e38f;
    }

    __shared__ float4 sq[256];
    int qbase = qq * 1024;
    for (int qt = 0; qt < 4; qt++) {
        int j = qbase + qt * 256 + tid;
        float qx = Bq[j*3+0], qy = Bq[j*3+1], qz = Bq[j*3+2];
        sq[tid] = make_float4(tf32r(qx), tf32r(qy), tf32r(qz),
                              qx*qx + qy*qy + qz*qz);
        __syncthreads();
#pragma unroll 4
        for (int k = 0; k < 256; k++) {
            float4 q = sq[k];
#pragma unroll
            for (int r = 0; r < 4; r++) {
                float dot = __fmul_rn(q.x, tpx[r]);
                dot = __fmaf_rn(q.y, tpy[r], dot);
                dot = __fmaf_rn(q.z, tpz[r], dot);
                float d = __fmaf_rn(-2.0f, dot, ppv[r] + q.w);
                mind[r] = fminf(mind[r], d);
            }
        }
        __syncthreads();
    }
#pragma unroll
    for (int r = 0; r < 4; r++) {
        int i = itile * 1024 + r * 256 + tid;
        g_pmin[(seg * 4 + qq) * NS + i] = mind[r];
    }
}

__global__ void __launch_bounds__(256) k_combine()
{
    int t = blockIdx.x * 256 + threadIdx.x;   // 0..32767
    int seg = t >> 12, i = t & (NS - 1);
    const float* pm = g_pmin + seg * 4 * NS + i;
    float m = fminf(fminf(pm[0], pm[NS]), fminf(pm[2 * NS], pm[3 * NS]));
    __shared__ double sd[256];
    sd[threadIdx.x] = (double)m;
    __syncthreads();
    for (int off = 128; off > 0; off >>= 1) {
        if (threadIdx.x < off) sd[threadIdx.x] += sd[threadIdx.x + off];
        __syncthreads();
    }
    if (threadIdx.x == 0) atomicAdd(&g_acc, sd[0]);
}

__global__ void k_final(float* out)
{
    out[0] = (float)(g_acc * (1.0 / 16384.0));   // mean(d1)+mean(d2), CHAMFER_W=1
}

// ---------------- launch ----------------
extern "C" void kernel_launch(void* const* d_in, const int* in_sizes, int n_in,
                              void* d_out, int out_size)
{
    const float* pv = (const float*)d_in[0];
    const void*  pf = (const void*)d_in[1];
    const float* gv = (const float*)d_in[2];
    const void*  gf = (const void*)d_in[3];

    // Partitionable (foldlike) split: key_i = threefry(key, (0, i)), both
    // outputs form the new key. key(42) = (0, 42).
    Keys keys;
    for (int b = 0; b < 4; b++) {
        unsigned kb0, kb1;
        tf2x32(0u, 42u, 0u, (unsigned)b, kb0, kb1);
        tf2x32(kb0, kb1, 0u, 0u, keys.k1[b][0], keys.k1[b][1]);
        tf2x32(kb0, kb1, 0u, 1u, keys.k2[b][0], keys.k2[b][1]);
        tf2x32(kb0, kb1, 0u, 2u, keys.k3[b][0], keys.k3[b][1]);
    }

    k_detect<<<1, 32>>>((const int*)pf);
    k_area<<<(2 * NB * NF + 255) / 256, 256>>>(pv, pf, gv, gf);
    k_argmin<<<NB * NS / 4, 128>>>(keys);
    k_points<<<(NB * NS + 63) / 64, 64>>>(keys, pv, pf, gv, gf);
    k_chamfer<<<128, 256>>>();
    k_combine<<<128, 256>>>();
    k_final<<<1, 1>>>((float*)d_out);
}

// round 12
// speedup vs baseline: 1.0674x; 1.0204x over previous
#include <cuda_runtime.h>

#define NB 4
#define NV 6890
#define NF 13776
#define NS 4096

struct Keys {
    unsigned k1[NB][2];
    unsigned k2[NB][2];
    unsigned k3[NB][2];
};

__device__ float2   g_invw2[NB * NF];        // (wpred, wgt) interleaved
__device__ float    g_pts [2 * NB * NS * 3];
__device__ float    g_pmin[8 * 4 * NS];      // [seg][qquarter][i]
__device__ double   g_acc;
__device__ int      g_is64;
__device__ unsigned g_one = 1;               // opaque 1: forces IMAD, not IADD3

// ---------------- threefry2x32 (20 rounds), exact JAX semantics ----------------
__host__ __device__ __forceinline__ void tf2x32(unsigned k0, unsigned k1,
                                                unsigned c0, unsigned c1,
                                                unsigned &o0, unsigned &o1)
{
    unsigned ks2 = k0 ^ k1 ^ 0x1BD11BDAu;
    unsigned x0 = c0 + k0;
    unsigned x1 = c1 + k1;
#if defined(__CUDA_ARCH__)
#define TF_ROTL(x, r) __funnelshift_l((x), (x), (r))
#else
#define TF_ROTL(x, r) (((x) << (r)) | ((x) >> (32 - (r))))
#endif
#define TF_RND(r) { x0 += x1; x1 = TF_ROTL(x1, r); x1 ^= x0; }
    TF_RND(13) TF_RND(15) TF_RND(26) TF_RND(6)
    x0 += k1;  x1 += ks2 + 1u;
    TF_RND(17) TF_RND(29) TF_RND(16) TF_RND(24)
    x0 += ks2; x1 += k0 + 2u;
    TF_RND(13) TF_RND(15) TF_RND(26) TF_RND(6)
    x0 += k0;  x1 += k1 + 3u;
    TF_RND(17) TF_RND(29) TF_RND(16) TF_RND(24)
    x0 += k1;  x1 += ks2 + 4u;
    TF_RND(13) TF_RND(15) TF_RND(26) TF_RND(6)
    x0 += ks2; x1 += k0 + 5u;
#undef TF_RND
#undef TF_ROTL
    o0 = x0; o1 = x1;
}

// partitionable random_bits (32-bit): counter = (0, flat_index), out = x0 ^ x1
__host__ __device__ __forceinline__ unsigned tf_bits(unsigned k0, unsigned k1,
                                                     unsigned e)
{
    unsigned o0, o1;
    tf2x32(k0, k1, 0u, e, o0, o1);
    return o0 ^ o1;
}

// Pipe-balanced threefry for c0=0: integer adds forced onto the fma pipe as
// IMAD (mad.lo with opaque one); SHF/LOP3 stay on the alu pipe.
// Caller passes cnt = e + k1 (pre-added).
#define MADD(d, a) asm("mad.lo.u32 %0, %1, %2, %0;" : "+r"(d) : "r"(a), "r"(one))

__device__ __forceinline__ unsigned tf_fast(unsigned k0, unsigned k1, unsigned ks2,
                                            unsigned B1, unsigned B2, unsigned B3,
                                            unsigned B4, unsigned B5,
                                            unsigned cnt, unsigned one)
{
    unsigned x0 = k0;        // 0 + k0
    unsigned x1 = cnt;       // e + k1 (pre-added by caller)
#define TFR(r) { MADD(x0, x1); x1 = __funnelshift_l(x1, x1, r) ^ x0; }
    TFR(13) TFR(15) TFR(26) TFR(6)
    MADD(x0, k1);  MADD(x1, B1);
    TFR(17) TFR(29) TFR(16) TFR(24)
    MADD(x0, ks2); MADD(x1, B2);
    TFR(13) TFR(15) TFR(26) TFR(6)
    MADD(x0, k0);  MADD(x1, B3);
    TFR(17) TFR(29) TFR(16) TFR(24)
    MADD(x0, k1);  MADD(x1, B4);
    TFR(13) TFR(15) TFR(26) TFR(6)
    MADD(x0, ks2); MADD(x1, B5);
#undef TFR
    return x0 ^ x1;
}

// -------- accurate -log(u'), u' = (m==0 ? tiny : m*2^-23), ~1-2 ulp relative ----
__device__ __forceinline__ float neglog_u(unsigned m)  // m = bits >> 9
{
    float u;
    if (m == 0u) u = 1.17549435e-38f;                         // finfo(f32).tiny
    else         u = __uint_as_float(0x3f800000u | m) - 1.0f; // exact
    unsigned bi = __float_as_uint(u);
    int e = (int)(bi >> 23) - 126;                            // u = x0*2^e, x0 in [0.5,1)
    float x = __uint_as_float((bi & 0x007fffffu) | (126u << 23));
    if (x < 0.70710678f) { x = x + x; e -= 1; }               // x in [0.7071, 1.4142)
    float s = __fdiv_rn(x - 1.0f, x + 1.0f);                  // x-1 exact (Sterbenz)
    float t = s * s;
    float P = __fmaf_rn(t, __fmaf_rn(t, __fmaf_rn(t, 0.11111111f, 0.14285715f),
                                     0.2f), 0.33333334f);
    float q = s + s;
    float lnx = __fmaf_rn(q * t, P, q);                       // ln x = 2s + 2s*t*P
    float kf = (float)e;
    float r = __fmaf_rn(kf, -2.12194440e-4f, lnx);            // ln2_lo
    r = __fmaf_rn(kf, 0.693359375f, r);                       // ln2_hi
    return -r;
}

// ---------------- tf32 rounding (RNA, matches cvt.rna.tf32.f32) ----------------
__device__ __forceinline__ float tf32r(float x)
{
    unsigned b = __float_as_uint(x);
    b = (b + 0x1000u) & 0xffffe000u;
    return __uint_as_float(b);
}

// ---------------- faces dtype detection (int32 vs int64) + zero ----------------
__global__ void k_detect(const int* __restrict__ pf32)
{
    if (threadIdx.x == 0) {
        int is64 = 1;
        for (int i = 0; i < 64; i++)
            if (pf32[2 * i + 1] != 0) { is64 = 0; break; }
        g_is64 = is64;
        g_acc = 0.0;
    }
}

__device__ __forceinline__ void load_face(const void* faces, long long fe,
                                          int &i0, int &i1, int &i2, int is64)
{
    if (is64) {
        const long long* p = (const long long*)faces + fe * 3;
        i0 = (int)p[0]; i1 = (int)p[1]; i2 = (int)p[2];
    } else {
        const int* p = (const int*)faces + fe * 3;
        i0 = p[0]; i1 = p[1]; i2 = p[2];
    }
}

// ---------------- per-face inverse (area + 1e-12) ----------------
__global__ void k_area(const float* __restrict__ pv, const void* __restrict__ pf,
                       const float* __restrict__ gv, const void* __restrict__ gf)
{
    int t = blockIdx.x * blockDim.x + threadIdx.x;
    if (t >= 2 * NB * NF) return;
    int is64 = g_is64;
    int type = t / (NB * NF);
    int rem  = t - type * (NB * NF);
    int b = rem / NF, f = rem - b * NF;
    const float* verts = (type ? gv : pv) + (size_t)b * NV * 3;
    int i0, i1, i2;
    load_face(type ? gf : pf, (long long)b * NF + f, i0, i1, i2, is64);
    float v0x = verts[i0*3+0], v0y = verts[i0*3+1], v0z = verts[i0*3+2];
    float ax = verts[i1*3+0] - v0x, ay = verts[i1*3+1] - v0y, az = verts[i1*3+2] - v0z;
    float bx = verts[i2*3+0] - v0x, by = verts[i2*3+1] - v0y, bz = verts[i2*3+2] - v0z;
    float cx = ay * bz - az * by;
    float cy = az * bx - ax * bz;
    float cz = ax * by - ay * bx;
    float cn = __fsqrt_rn(cx * cx + cy * cy + cz * cz);
    ((float*)g_invw2)[(b * NF + f) * 2 + type] = __fdiv_rn(1.0f, 0.5f * cn + 1e-12f);
}

// ---------------- gumbel-argmin + fused point generation ----------------
// Inner loop is the R9 configuration verbatim (best measured: 765 us).
// Prefilter with cheap lower bounds (rn((1-u)w) <= rn(-lnu*w), rn monotone)
// against pre-group bests (superset of per-candidate tests); exact sequential
// compares inside decide. Bit-identical to evaluating every candidate.
#define PROCESS2(bits1, bits2, wva, wvb, fcur) {                                \
    unsigned m1 = (bits1) >> 9, m2 = (bits2) >> 9;                              \
    float yl1 = 2.0f - __uint_as_float(0x3f800000u | m1);                       \
    float yl2 = 2.0f - __uint_as_float(0x3f800000u | m2);                       \
    float c0a = __fmul_rn(yl1, (wva).x), c1a = __fmul_rn(yl1, (wva).y);         \
    float c0b = __fmul_rn(yl2, (wvb).x), c1b = __fmul_rn(yl2, (wvb).y);         \
    if (fminf(c0a, c0b) < bb0f || fminf(c1a, c1b) < bb1f) {                     \
        float lg1 = neglog_u(m1);                                               \
        float lg2 = neglog_u(m2);                                               \
        float t0 = __fmul_rn(lg1, (wva).x);                                     \
        if (t0 < bb0f) { bb0f = t0; bf0 = (fcur); }                             \
        float t1 = __fmul_rn(lg1, (wva).y);                                     \
        if (t1 < bb1f) { bb1f = t1; bf1 = (fcur); }                             \
        float t2 = __fmul_rn(lg2, (wvb).x);                                     \
        if (t2 < bb0f) { bb0f = t2; bf0 = (fcur) + 32; }                        \
        float t3 = __fmul_rn(lg2, (wvb).y);                                     \
        if (t3 < bb1f) { bb1f = t3; bf1 = (fcur) + 32; }                        \
    } }

__global__ void __launch_bounds__(128, 14) k_argmin(
    Keys keys,
    const float* __restrict__ pv, const void* __restrict__ pf,
    const float* __restrict__ gv, const void* __restrict__ gf)
{
    unsigned one = g_one;
    int gw   = blockIdx.x * 4 + (threadIdx.x >> 5);  // global warp = row id
    int lane = threadIdx.x & 31;
    int b = gw >> 12;                                // 4096 rows per batch
    int i = gw & (NS - 1);
    unsigned k0 = keys.k1[b][0], k1 = keys.k1[b][1];
    unsigned ks2 = k0 ^ k1 ^ 0x1BD11BDAu;
    unsigned B1 = ks2 + 1u, B2 = k0 + 2u, B3 = k1 + 3u, B4 = ks2 + 4u, B5 = k0 + 5u;
    const float2* __restrict__ w2 = g_invw2 + b * NF;
    float bb0f = 3.402823466e38f, bb1f = 3.402823466e38f;
    int bf0 = NF, bf1 = NF;
    unsigned eoff = (unsigned)i * (unsigned)NF + k1;

    int f1 = lane;
    unsigned cnt1 = eoff + (unsigned)lane;

    // 215 iterations x 2 chains (215 x 64 = 13760), tail 16
    for (int t = 0; t < 215; t++) {
        unsigned bits1 = tf_fast(k0, k1, ks2, B1, B2, B3, B4, B5, cnt1,       one);
        unsigned bits2 = tf_fast(k0, k1, ks2, B1, B2, B3, B4, B5, cnt1 + 32u, one);
        float2 wa = __ldg(w2 + f1);
        float2 wb = __ldg(w2 + f1 + 32);
        PROCESS2(bits1, bits2, wa, wb, f1)
        f1 += 64;
        MADD(cnt1, 64u);
    }
    if (lane < 16) {                                  // f in [13760, 13776)
        unsigned bits = tf_fast(k0, k1, ks2, B1, B2, B3, B4, B5, cnt1, one);
        float2 wt = __ldg(w2 + f1);
        unsigned m = bits >> 9;
        float yl = 2.0f - __uint_as_float(0x3f800000u | m);
        float c0 = __fmul_rn(yl, wt.x), c1 = __fmul_rn(yl, wt.y);
        if (c0 < bb0f || c1 < bb1f) {
            float lg = neglog_u(m);
            float t0 = __fmul_rn(lg, wt.x);
            if (t0 < bb0f) { bb0f = t0; bf0 = f1; }
            float t1 = __fmul_rn(lg, wt.y);
            if (t1 < bb1f) { bb1f = t1; bf1 = f1; }
        }
    }

#pragma unroll
    for (int off = 16; off > 0; off >>= 1) {
        float ob; int of;
        ob = __shfl_down_sync(0xffffffffu, bb0f, off);
        of = __shfl_down_sync(0xffffffffu, bf0, off);
        if (ob < bb0f || (ob == bb0f && of < bf0)) { bb0f = ob; bf0 = of; }
        ob = __shfl_down_sync(0xffffffffu, bb1f, off);
        of = __shfl_down_sync(0xffffffffu, bf1, off);
        if (ob < bb1f || (ob == bb1f && of < bf1)) { bb1f = ob; bf1 = of; }
    }

    // ---- fused point generation (once per row; lanes 0/1 handle pred/gt) ----
    int wf0 = __shfl_sync(0xffffffffu, bf0, 0);
    int wf1 = __shfl_sync(0xffffffffu, bf1, 0);
    unsigned myb = 0;
    if (lane < 2) {
        // lane 0: u-bits (key2); lane 1: w-bits (key3)
        unsigned kk0 = lane ? keys.k3[b][0] : keys.k2[b][0];
        unsigned kk1 = lane ? keys.k3[b][1] : keys.k2[b][1];
        myb = tf_bits(kk0, kk1, (unsigned)i);
    }
    unsigned bu = __shfl_sync(0xffffffffu, myb, 0);
    unsigned bw = __shfl_sync(0xffffffffu, myb, 1);
    if (lane < 2) {
        int is64 = g_is64;
        int type = lane;
        int f = type ? wf1 : wf0;
        float u = __uint_as_float(0x3f800000u | (bu >> 9)) - 1.0f;
        float w = __uint_as_float(0x3f800000u | (bw >> 9)) - 1.0f;
        float r = __fsqrt_rn(u);
        float a0 = 1.0f - r;
        float a1 = __fmul_rn(r, 1.0f - w);
        float a2 = __fmul_rn(r, w);
        const float* verts = (type ? gv : pv) + (size_t)b * NV * 3;
        int i0, i1, i2;
        load_face(type ? gf : pf, (long long)b * NF + f, i0, i1, i2, is64);
        float* dst = g_pts + ((size_t)(type * NB + b) * NS + i) * 3;
#pragma unroll
        for (int c = 0; c < 3; c++)
            dst[c] = a0 * verts[i0*3+c] + a1 * verts[i1*3+c] + a2 * verts[i2*3+c];
    }
}

// ---------------- brute-force two-way chamfer, TF32-emulated dot ----------------
__global__ void __launch_bounds__(256) k_chamfer()
{
    int blk   = blockIdx.x;        // 128
    int itile = blk & 3;
    int qq    = (blk >> 2) & 3;
    int seg   = blk >> 4;          // 0..7 : b*2 + dir
    int b = seg >> 1, dir = seg & 1;
    const float* __restrict__ A  = g_pts + (size_t)((dir ? NB : 0) + b) * NS * 3;
    const float* __restrict__ Bq = g_pts + (size_t)((dir ? 0 : NB) + b) * NS * 3;
    int tid = threadIdx.x;

    float tpx[4], tpy[4], tpz[4], ppv[4], mind[4];
#pragma unroll
    for (int r = 0; r < 4; r++) {
        int i = itile * 1024 + r * 256 + tid;
        float px = A[i*3+0], py = A[i*3+1], pz = A[i*3+2];
        ppv[r] = px*px + py*py + pz*pz;              // exact f32 (outside GEMM)
        tpx[r] = tf32r(px); tpy[r] = tf32r(py); tpz[r] = tf32r(pz);
        mind[r] = 3.4e38f;
    }

    __shared__ float4 sq[256];
    int qbase = qq * 1024;
    for (int qt = 0; qt < 4; qt++) {
        int j = qbase + qt * 256 + tid;
        float qx = Bq[j*3+0], qy = Bq[j*3+1], qz = Bq[j*3+2];
        sq[tid] = make_float4(tf32r(qx), tf32r(qy), tf32r(qz),
                              qx*qx + qy*qy + qz*qz);
        __syncthreads();
#pragma unroll 4
        for (int k = 0; k < 256; k++) {
            float4 q = sq[k];
#pragma unroll
            for (int r = 0; r < 4; r++) {
                float dot = __fmul_rn(q.x, tpx[r]);
                dot = __fmaf_rn(q.y, tpy[r], dot);
                dot = __fmaf_rn(q.z, tpz[r], dot);
                float d = __fmaf_rn(-2.0f, dot, ppv[r] + q.w);
                mind[r] = fminf(mind[r], d);
            }
        }
        __syncthreads();
    }
#pragma unroll
    for (int r = 0; r < 4; r++) {
        int i = itile * 1024 + r * 256 + tid;
        g_pmin[(seg * 4 + qq) * NS + i] = mind[r];
    }
}

__global__ void __launch_bounds__(256) k_combine()
{
    int t = blockIdx.x * 256 + threadIdx.x;   // 0..32767
    int seg = t >> 12, i = t & (NS - 1);
    const float* pm = g_pmin + seg * 4 * NS + i;
    float m = fminf(fminf(pm[0], pm[NS]), fminf(pm[2 * NS], pm[3 * NS]));
    __shared__ double sd[256];
    sd[threadIdx.x] = (double)m;
    __syncthreads();
    for (int off = 128; off > 0; off >>= 1) {
        if (threadIdx.x < off) sd[threadIdx.x] += sd[threadIdx.x + off];
        __syncthreads();
    }
    if (threadIdx.x == 0) atomicAdd(&g_acc, sd[0]);
}

__global__ void k_final(float* out)
{
    out[0] = (float)(g_acc * (1.0 / 16384.0));   // mean(d1)+mean(d2), CHAMFER_W=1
}

// ---------------- launch ----------------
extern "C" void kernel_launch(void* const* d_in, const int* in_sizes, int n_in,
                              void* d_out, int out_size)
{
    const float* pv = (const float*)d_in[0];
    const void*  pf = (const void*)d_in[1];
    const float* gv = (const float*)d_in[2];
    const void*  gf = (const void*)d_in[3];

    // Partitionable (foldlike) split: key_i = threefry(key, (0, i)), both
    // outputs form the new key. key(42) = (0, 42).
    Keys keys;
    for (int b = 0; b < 4; b++) {
        unsigned kb0, kb1;
        tf2x32(0u, 42u, 0u, (unsigned)b, kb0, kb1);
        tf2x32(kb0, kb1, 0u, 0u, keys.k1[b][0], keys.k1[b][1]);
        tf2x32(kb0, kb1, 0u, 1u, keys.k2[b][0], keys.k2[b][1]);
        tf2x32(kb0, kb1, 0u, 2u, keys.k3[b][0], keys.k3[b][1]);
    }

    k_detect<<<1, 32>>>((const int*)pf);
    k_area<<<(2 * NB * NF + 255) / 256, 256>>>(pv, pf, gv, gf);
    k_argmin<<<NB * NS / 4, 128>>>(keys, pv, pf, gv, gf);
    k_chamfer<<<128, 256>>>();
    k_combine<<<128, 256>>>();
    k_final<<<1, 1>>>((float*)d_out);
}

// round 13
// speedup vs baseline: 1.0736x; 1.0058x over previous
#include <cuda_runtime.h>

#define NB 4
#define NV 6890
#define NF 13776
#define NS 4096

struct Keys {
    unsigned k1[NB][2];
    unsigned k2[NB][2];
    unsigned k3[NB][2];
};

__device__ float2   g_invw2[NB * NF];        // (wpred, wgt) interleaved
__device__ float    g_pts [2 * NB * NS * 3];
__device__ float    g_pmin[8 * 16 * NS];     // [seg][qtile][i]
__device__ double   g_acc;
__device__ int      g_is64;
__device__ unsigned g_one = 1;               // opaque 1: forces IMAD, not IADD3

// ---------------- threefry2x32 (20 rounds), exact JAX semantics ----------------
__host__ __device__ __forceinline__ void tf2x32(unsigned k0, unsigned k1,
                                                unsigned c0, unsigned c1,
                                                unsigned &o0, unsigned &o1)
{
    unsigned ks2 = k0 ^ k1 ^ 0x1BD11BDAu;
    unsigned x0 = c0 + k0;
    unsigned x1 = c1 + k1;
#if defined(__CUDA_ARCH__)
#define TF_ROTL(x, r) __funnelshift_l((x), (x), (r))
#else
#define TF_ROTL(x, r) (((x) << (r)) | ((x) >> (32 - (r))))
#endif
#define TF_RND(r) { x0 += x1; x1 = TF_ROTL(x1, r); x1 ^= x0; }
    TF_RND(13) TF_RND(15) TF_RND(26) TF_RND(6)
    x0 += k1;  x1 += ks2 + 1u;
    TF_RND(17) TF_RND(29) TF_RND(16) TF_RND(24)
    x0 += ks2; x1 += k0 + 2u;
    TF_RND(13) TF_RND(15) TF_RND(26) TF_RND(6)
    x0 += k0;  x1 += k1 + 3u;
    TF_RND(17) TF_RND(29) TF_RND(16) TF_RND(24)
    x0 += k1;  x1 += ks2 + 4u;
    TF_RND(13) TF_RND(15) TF_RND(26) TF_RND(6)
    x0 += ks2; x1 += k0 + 5u;
#undef TF_RND
#undef TF_ROTL
    o0 = x0; o1 = x1;
}

// partitionable random_bits (32-bit): counter = (0, flat_index), out = x0 ^ x1
__host__ __device__ __forceinline__ unsigned tf_bits(unsigned k0, unsigned k1,
                                                     unsigned e)
{
    unsigned o0, o1;
    tf2x32(k0, k1, 0u, e, o0, o1);
    return o0 ^ o1;
}

// Pipe-balanced threefry for c0=0: integer adds forced onto the fma pipe as
// IMAD (mad.lo with opaque one); SHF/LOP3 stay on the alu pipe.
// Caller passes cnt = e + k1 (pre-added).
#define MADD(d, a) asm("mad.lo.u32 %0, %1, %2, %0;" : "+r"(d) : "r"(a), "r"(one))

__device__ __forceinline__ unsigned tf_fast(unsigned k0, unsigned k1, unsigned ks2,
                                            unsigned B1, unsigned B2, unsigned B3,
                                            unsigned B4, unsigned B5,
                                            unsigned cnt, unsigned one)
{
    unsigned x0 = k0;        // 0 + k0
    unsigned x1 = cnt;       // e + k1 (pre-added by caller)
#define TFR(r) { MADD(x0, x1); x1 = __funnelshift_l(x1, x1, r) ^ x0; }
    TFR(13) TFR(15) TFR(26) TFR(6)
    MADD(x0, k1);  MADD(x1, B1);
    TFR(17) TFR(29) TFR(16) TFR(24)
    MADD(x0, ks2); MADD(x1, B2);
    TFR(13) TFR(15) TFR(26) TFR(6)
    MADD(x0, k0);  MADD(x1, B3);
    TFR(17) TFR(29) TFR(16) TFR(24)
    MADD(x0, k1);  MADD(x1, B4);
    TFR(13) TFR(15) TFR(26) TFR(6)
    MADD(x0, ks2); MADD(x1, B5);
#undef TFR
    return x0 ^ x1;
}

// -------- accurate -log(u'), u' = (m==0 ? tiny : m*2^-23), ~1-2 ulp relative ----
__device__ __forceinline__ float neglog_u(unsigned m)  // m = bits >> 9
{
    float u;
    if (m == 0u) u = 1.17549435e-38f;                         // finfo(f32).tiny
    else         u = __uint_as_float(0x3f800000u | m) - 1.0f; // exact
    unsigned bi = __float_as_uint(u);
    int e = (int)(bi >> 23) - 126;                            // u = x0*2^e, x0 in [0.5,1)
    float x = __uint_as_float((bi & 0x007fffffu) | (126u << 23));
    if (x < 0.70710678f) { x = x + x; e -= 1; }               // x in [0.7071, 1.4142)
    float s = __fdiv_rn(x - 1.0f, x + 1.0f);                  // x-1 exact (Sterbenz)
    float t = s * s;
    float P = __fmaf_rn(t, __fmaf_rn(t, __fmaf_rn(t, 0.11111111f, 0.14285715f),
                                     0.2f), 0.33333334f);
    float q = s + s;
    float lnx = __fmaf_rn(q * t, P, q);                       // ln x = 2s + 2s*t*P
    float kf = (float)e;
    float r = __fmaf_rn(kf, -2.12194440e-4f, lnx);            // ln2_lo
    r = __fmaf_rn(kf, 0.693359375f, r);                       // ln2_hi
    return -r;
}

// ---------------- tf32 rounding (RNA, matches cvt.rna.tf32.f32) ----------------
__device__ __forceinline__ float tf32r(float x)
{
    unsigned b = __float_as_uint(x);
    b = (b + 0x1000u) & 0xffffe000u;
    return __uint_as_float(b);
}

// ---------------- faces dtype detection (int32 vs int64) + zero ----------------
__global__ void k_detect(const int* __restrict__ pf32)
{
    if (threadIdx.x == 0) {
        int is64 = 1;
        for (int i = 0; i < 64; i++)
            if (pf32[2 * i + 1] != 0) { is64 = 0; break; }
        g_is64 = is64;
        g_acc = 0.0;
    }
}

__device__ __forceinline__ void load_face(const void* faces, long long fe,
                                          int &i0, int &i1, int &i2, int is64)
{
    if (is64) {
        const long long* p = (const long long*)faces + fe * 3;
        i0 = (int)p[0]; i1 = (int)p[1]; i2 = (int)p[2];
    } else {
        const int* p = (const int*)faces + fe * 3;
        i0 = p[0]; i1 = p[1]; i2 = p[2];
    }
}

// ---------------- per-face inverse (area + 1e-12) ----------------
__global__ void k_area(const float* __restrict__ pv, const void* __restrict__ pf,
                       const float* __restrict__ gv, const void* __restrict__ gf)
{
    int t = blockIdx.x * blockDim.x + threadIdx.x;
    if (t >= 2 * NB * NF) return;
    int is64 = g_is64;
    int type = t / (NB * NF);
    int rem  = t - type * (NB * NF);
    int b = rem / NF, f = rem - b * NF;
    const float* verts = (type ? gv : pv) + (size_t)b * NV * 3;
    int i0, i1, i2;
    load_face(type ? gf : pf, (long long)b * NF + f, i0, i1, i2, is64);
    float v0x = verts[i0*3+0], v0y = verts[i0*3+1], v0z = verts[i0*3+2];
    float ax = verts[i1*3+0] - v0x, ay = verts[i1*3+1] - v0y, az = verts[i1*3+2] - v0z;
    float bx = verts[i2*3+0] - v0x, by = verts[i2*3+1] - v0y, bz = verts[i2*3+2] - v0z;
    float cx = ay * bz - az * by;
    float cy = az * bx - ax * bz;
    float cz = ax * by - ay * bx;
    float cn = __fsqrt_rn(cx * cx + cy * cy + cz * cz);
    ((float*)g_invw2)[(b * NF + f) * 2 + type] = __fdiv_rn(1.0f, 0.5f * cn + 1e-12f);
}

// ---------------- gumbel-argmin + fused point generation ----------------
// Inner loop is the R9 configuration verbatim (best measured: 765 us).
#define PROCESS2(bits1, bits2, wva, wvb, fcur) {                                \
    unsigned m1 = (bits1) >> 9, m2 = (bits2) >> 9;                              \
    float yl1 = 2.0f - __uint_as_float(0x3f800000u | m1);                       \
    float yl2 = 2.0f - __uint_as_float(0x3f800000u | m2);                       \
    float c0a = __fmul_rn(yl1, (wva).x), c1a = __fmul_rn(yl1, (wva).y);         \
    float c0b = __fmul_rn(yl2, (wvb).x), c1b = __fmul_rn(yl2, (wvb).y);         \
    if (fminf(c0a, c0b) < bb0f || fminf(c1a, c1b) < bb1f) {                     \
        float lg1 = neglog_u(m1);                                               \
        float lg2 = neglog_u(m2);                                               \
        float t0 = __fmul_rn(lg1, (wva).x);                                     \
        if (t0 < bb0f) { bb0f = t0; bf0 = (fcur); }                             \
        float t1 = __fmul_rn(lg1, (wva).y);                                     \
        if (t1 < bb1f) { bb1f = t1; bf1 = (fcur); }                             \
        float t2 = __fmul_rn(lg2, (wvb).x);                                     \
        if (t2 < bb0f) { bb0f = t2; bf0 = (fcur) + 32; }                        \
        float t3 = __fmul_rn(lg2, (wvb).y);                                     \
        if (t3 < bb1f) { bb1f = t3; bf1 = (fcur) + 32; }                        \
    } }

__global__ void __launch_bounds__(128, 14) k_argmin(
    Keys keys,
    const float* __restrict__ pv, const void* __restrict__ pf,
    const float* __restrict__ gv, const void* __restrict__ gf)
{
    unsigned one = g_one;
    int gw   = blockIdx.x * 4 + (threadIdx.x >> 5);  // global warp = row id
    int lane = threadIdx.x & 31;
    int b = gw >> 12;                                // 4096 rows per batch
    int i = gw & (NS - 1);
    unsigned k0 = keys.k1[b][0], k1 = keys.k1[b][1];
    unsigned ks2 = k0 ^ k1 ^ 0x1BD11BDAu;
    unsigned B1 = ks2 + 1u, B2 = k0 + 2u, B3 = k1 + 3u, B4 = ks2 + 4u, B5 = k0 + 5u;
    const float2* __restrict__ w2 = g_invw2 + b * NF;
    float bb0f = 3.402823466e38f, bb1f = 3.402823466e38f;
    int bf0 = NF, bf1 = NF;
    unsigned eoff = (unsigned)i * (unsigned)NF + k1;

    int f1 = lane;
    unsigned cnt1 = eoff + (unsigned)lane;

    // 215 iterations x 2 chains (215 x 64 = 13760), tail 16
    for (int t = 0; t < 215; t++) {
        unsigned bits1 = tf_fast(k0, k1, ks2, B1, B2, B3, B4, B5, cnt1,       one);
        unsigned bits2 = tf_fast(k0, k1, ks2, B1, B2, B3, B4, B5, cnt1 + 32u, one);
        float2 wa = __ldg(w2 + f1);
        float2 wb = __ldg(w2 + f1 + 32);
        PROCESS2(bits1, bits2, wa, wb, f1)
        f1 += 64;
        MADD(cnt1, 64u);
    }
    if (lane < 16) {                                  // f in [13760, 13776)
        unsigned bits = tf_fast(k0, k1, ks2, B1, B2, B3, B4, B5, cnt1, one);
        float2 wt = __ldg(w2 + f1);
        unsigned m = bits >> 9;
        float yl = 2.0f - __uint_as_float(0x3f800000u | m);
        float c0 = __fmul_rn(yl, wt.x), c1 = __fmul_rn(yl, wt.y);
        if (c0 < bb0f || c1 < bb1f) {
            float lg = neglog_u(m);
            float t0 = __fmul_rn(lg, wt.x);
            if (t0 < bb0f) { bb0f = t0; bf0 = f1; }
            float t1 = __fmul_rn(lg, wt.y);
            if (t1 < bb1f) { bb1f = t1; bf1 = f1; }
        }
    }

#pragma unroll
    for (int off = 16; off > 0; off >>= 1) {
        float ob; int of;
        ob = __shfl_down_sync(0xffffffffu, bb0f, off);
        of = __shfl_down_sync(0xffffffffu, bf0, off);
        if (ob < bb0f || (ob == bb0f && of < bf0)) { bb0f = ob; bf0 = of; }
        ob = __shfl_down_sync(0xffffffffu, bb1f, off);
        of = __shfl_down_sync(0xffffffffu, bf1, off);
        if (ob < bb1f || (ob == bb1f && of < bf1)) { bb1f = ob; bf1 = of; }
    }

    // ---- fused point generation (once per row; lanes 0/1 handle pred/gt) ----
    int wf0 = __shfl_sync(0xffffffffu, bf0, 0);
    int wf1 = __shfl_sync(0xffffffffu, bf1, 0);
    unsigned myb = 0;
    if (lane < 2) {
        // lane 0: u-bits (key2); lane 1: w-bits (key3)
        unsigned kk0 = lane ? keys.k3[b][0] : keys.k2[b][0];
        unsigned kk1 = lane ? keys.k3[b][1] : keys.k2[b][1];
        myb = tf_bits(kk0, kk1, (unsigned)i);
    }
    unsigned bu = __shfl_sync(0xffffffffu, myb, 0);
    unsigned bw = __shfl_sync(0xffffffffu, myb, 1);
    if (lane < 2) {
        int is64 = g_is64;
        int type = lane;
        int f = type ? wf1 : wf0;
        float u = __uint_as_float(0x3f800000u | (bu >> 9)) - 1.0f;
        float w = __uint_as_float(0x3f800000u | (bw >> 9)) - 1.0f;
        float r = __fsqrt_rn(u);
        float a0 = 1.0f - r;
        float a1 = __fmul_rn(r, 1.0f - w);
        float a2 = __fmul_rn(r, w);
        const float* verts = (type ? gv : pv) + (size_t)b * NV * 3;
        int i0, i1, i2;
        load_face(type ? gf : pf, (long long)b * NF + f, i0, i1, i2, is64);
        float* dst = g_pts + ((size_t)(type * NB + b) * NS + i) * 3;
#pragma unroll
        for (int c = 0; c < 3; c++)
            dst[c] = a0 * verts[i0*3+c] + a1 * verts[i1*3+c] + a2 * verts[i2*3+c];
    }
}

// ---------------- brute-force two-way chamfer, TF32-emulated dot ----------------
// 512 blocks: 8 segs x 4 i-tiles x 16 q-tiles of 256. Same arithmetic and
// same per-tile min order as before; partial mins combined in k_combine.
__global__ void __launch_bounds__(256) k_chamfer()
{
    int blk   = blockIdx.x;        // 512
    int itile = blk & 3;
    int qt    = (blk >> 2) & 15;
    int seg   = blk >> 6;          // 0..7 : b*2 + dir
    int b = seg >> 1, dir = seg & 1;
    const float* __restrict__ A  = g_pts + (size_t)((dir ? NB : 0) + b) * NS * 3;
    const float* __restrict__ Bq = g_pts + (size_t)((dir ? 0 : NB) + b) * NS * 3;
    int tid = threadIdx.x;

    float tpx[4], tpy[4], tpz[4], ppv[4], mind[4];
#pragma unroll
    for (int r = 0; r < 4; r++) {
        int i = itile * 1024 + r * 256 + tid;
        float px = A[i*3+0], py = A[i*3+1], pz = A[i*3+2];
        ppv[r] = px*px + py*py + pz*pz;              // exact f32 (outside GEMM)
        tpx[r] = tf32r(px); tpy[r] = tf32r(py); tpz[r] = tf32r(pz);
        mind[r] = 3.4e38f;
    }

    __shared__ float4 sq[256];
    {
        int j = qt * 256 + tid;
        float qx = Bq[j*3+0], qy = Bq[j*3+1], qz = Bq[j*3+2];
        sq[tid] = make_float4(tf32r(qx), tf32r(qy), tf32r(qz),
                              qx*qx + qy*qy + qz*qz);
    }
    __syncthreads();
#pragma unroll 4
    for (int k = 0; k < 256; k++) {
        float4 q = sq[k];
#pragma unroll
        for (int r = 0; r < 4; r++) {
            float dot = __fmul_rn(q.x, tpx[r]);
            dot = __fmaf_rn(q.y, tpy[r], dot);
            dot = __fmaf_rn(q.z, tpz[r], dot);
            float d = __fmaf_rn(-2.0f, dot, ppv[r] + q.w);
            mind[r] = fminf(mind[r], d);
        }
    }
#pragma unroll
    for (int r = 0; r < 4; r++) {
        int i = itile * 1024 + r * 256 + tid;
        g_pmin[(seg * 16 + qt) * NS + i] = mind[r];
    }
}

__global__ void __launch_bounds__(256) k_combine()
{
    int t = blockIdx.x * 256 + threadIdx.x;   // 0..32767
    int seg = t >> 12, i = t & (NS - 1);
    const float* pm = g_pmin + seg * 16 * NS + i;
    float m = 3.4e38f;
#pragma unroll
    for (int q = 0; q < 16; q++)
        m = fminf(m, pm[q * NS]);
    __shared__ double sd[256];
    sd[threadIdx.x] = (double)m;
    __syncthreads();
    for (int off = 128; off > 0; off >>= 1) {
        if (threadIdx.x < off) sd[threadIdx.x] += sd[threadIdx.x + off];
        __syncthreads();
    }
    if (threadIdx.x == 0) atomicAdd(&g_acc, sd[0]);
}

__global__ void k_final(float* out)
{
    out[0] = (float)(g_acc * (1.0 / 16384.0));   // mean(d1)+mean(d2), CHAMFER_W=1
}

// ---------------- launch ----------------
extern "C" void kernel_launch(void* const* d_in, const int* in_sizes, int n_in,
                              void* d_out, int out_size)
{
    const float* pv = (const float*)d_in[0];
    const void*  pf = (const void*)d_in[1];
    const float* gv = (const float*)d_in[2];
    const void*  gf = (const void*)d_in[3];

    // Partitionable (foldlike) split: key_i = threefry(key, (0, i)), both
    // outputs form the new key. key(42) = (0, 42).
    Keys keys;
    for (int b = 0; b < 4; b++) {
        unsigned kb0, kb1;
        tf2x32(0u, 42u, 0u, (unsigned)b, kb0, kb1);
        tf2x32(kb0, kb1, 0u, 0u, keys.k1[b][0], keys.k1[b][1]);
        tf2x32(kb0, kb1, 0u, 1u, keys.k2[b][0], keys.k2[b][1]);
        tf2x32(kb0, kb1, 0u, 2u, keys.k3[b][0], keys.k3[b][1]);
    }

    k_detect<<<1, 32>>>((const int*)pf);
    k_area<<<(2 * NB * NF + 255) / 256, 256>>>(pv, pf, gv, gf);
    k_argmin<<<NB * NS / 4, 128>>>(keys, pv, pf, gv, gf);
    k_chamfer<<<512, 256>>>();
    k_combine<<<128, 256>>>();
    k_final<<<1, 1>>>((float*)d_out);
}

// round 14
// speedup vs baseline: 1.0803x; 1.0063x over previous
#include <cuda_runtime.h>

#define NB 4
#define NV 6890
#define NF 13776
#define NS 4096

struct Keys {
    unsigned k1[NB][2];
    unsigned k2[NB][2];
    unsigned k3[NB][2];
};

__device__ float2   g_invw2[NB * NF];        // (wpred, wgt) interleaved
__device__ float    g_pts [2 * NB * NS * 3];
__device__ float    g_pmin[8 * 16 * NS];     // [seg][qtile][i]  (pp-hoisted)
__device__ double   g_acc;
__device__ int      g_is64;
__device__ unsigned g_one = 1;               // opaque 1: forces IMAD, not IADD3

// ---------------- threefry2x32 (20 rounds), exact JAX semantics ----------------
__host__ __device__ __forceinline__ void tf2x32(unsigned k0, unsigned k1,
                                                unsigned c0, unsigned c1,
                                                unsigned &o0, unsigned &o1)
{
    unsigned ks2 = k0 ^ k1 ^ 0x1BD11BDAu;
    unsigned x0 = c0 + k0;
    unsigned x1 = c1 + k1;
#if defined(__CUDA_ARCH__)
#define TF_ROTL(x, r) __funnelshift_l((x), (x), (r))
#else
#define TF_ROTL(x, r) (((x) << (r)) | ((x) >> (32 - (r))))
#endif
#define TF_RND(r) { x0 += x1; x1 = TF_ROTL(x1, r); x1 ^= x0; }
    TF_RND(13) TF_RND(15) TF_RND(26) TF_RND(6)
    x0 += k1;  x1 += ks2 + 1u;
    TF_RND(17) TF_RND(29) TF_RND(16) TF_RND(24)
    x0 += ks2; x1 += k0 + 2u;
    TF_RND(13) TF_RND(15) TF_RND(26) TF_RND(6)
    x0 += k0;  x1 += k1 + 3u;
    TF_RND(17) TF_RND(29) TF_RND(16) TF_RND(24)
    x0 += k1;  x1 += ks2 + 4u;
    TF_RND(13) TF_RND(15) TF_RND(26) TF_RND(6)
    x0 += ks2; x1 += k0 + 5u;
#undef TF_RND
#undef TF_ROTL
    o0 = x0; o1 = x1;
}

// partitionable random_bits (32-bit): counter = (0, flat_index), out = x0 ^ x1
__host__ __device__ __forceinline__ unsigned tf_bits(unsigned k0, unsigned k1,
                                                     unsigned e)
{
    unsigned o0, o1;
    tf2x32(k0, k1, 0u, e, o0, o1);
    return o0 ^ o1;
}

// Pipe-balanced threefry for c0=0: integer adds forced onto the fma pipe as
// IMAD (mad.lo with opaque one); SHF/LOP3 stay on the alu pipe.
// Caller passes cnt = e + k1 (pre-added).
#define MADD(d, a) asm("mad.lo.u32 %0, %1, %2, %0;" : "+r"(d) : "r"(a), "r"(one))

__device__ __forceinline__ unsigned tf_fast(unsigned k0, unsigned k1, unsigned ks2,
                                            unsigned B1, unsigned B2, unsigned B3,
                                            unsigned B4, unsigned B5,
                                            unsigned cnt, unsigned one)
{
    unsigned x0 = k0;        // 0 + k0
    unsigned x1 = cnt;       // e + k1 (pre-added by caller)
#define TFR(r) { MADD(x0, x1); x1 = __funnelshift_l(x1, x1, r) ^ x0; }
    TFR(13) TFR(15) TFR(26) TFR(6)
    MADD(x0, k1);  MADD(x1, B1);
    TFR(17) TFR(29) TFR(16) TFR(24)
    MADD(x0, ks2); MADD(x1, B2);
    TFR(13) TFR(15) TFR(26) TFR(6)
    MADD(x0, k0);  MADD(x1, B3);
    TFR(17) TFR(29) TFR(16) TFR(24)
    MADD(x0, k1);  MADD(x1, B4);
    TFR(13) TFR(15) TFR(26) TFR(6)
    MADD(x0, ks2); MADD(x1, B5);
#undef TFR
    return x0 ^ x1;
}

// -------- accurate -log(u'), u' = (m==0 ? tiny : m*2^-23), ~1-2 ulp relative ----
__device__ __forceinline__ float neglog_u(unsigned m)  // m = bits >> 9
{
    float u;
    if (m == 0u) u = 1.17549435e-38f;                         // finfo(f32).tiny
    else         u = __uint_as_float(0x3f800000u | m) - 1.0f; // exact
    unsigned bi = __float_as_uint(u);
    int e = (int)(bi >> 23) - 126;                            // u = x0*2^e, x0 in [0.5,1)
    float x = __uint_as_float((bi & 0x007fffffu) | (126u << 23));
    if (x < 0.70710678f) { x = x + x; e -= 1; }               // x in [0.7071, 1.4142)
    float s = __fdiv_rn(x - 1.0f, x + 1.0f);                  // x-1 exact (Sterbenz)
    float t = s * s;
    float P = __fmaf_rn(t, __fmaf_rn(t, __fmaf_rn(t, 0.11111111f, 0.14285715f),
                                     0.2f), 0.33333334f);
    float q = s + s;
    float lnx = __fmaf_rn(q * t, P, q);                       // ln x = 2s + 2s*t*P
    float kf = (float)e;
    float r = __fmaf_rn(kf, -2.12194440e-4f, lnx);            // ln2_lo
    r = __fmaf_rn(kf, 0.693359375f, r);                       // ln2_hi
    return -r;
}

// ---------------- tf32 rounding (RNA, matches cvt.rna.tf32.f32) ----------------
__device__ __forceinline__ float tf32r(float x)
{
    unsigned b = __float_as_uint(x);
    b = (b + 0x1000u) & 0xffffe000u;
    return __uint_as_float(b);
}

// ---------------- faces dtype detection (int32 vs int64) + zero ----------------
__global__ void k_detect(const int* __restrict__ pf32)
{
    if (threadIdx.x == 0) {
        int is64 = 1;
        for (int i = 0; i < 64; i++)
            if (pf32[2 * i + 1] != 0) { is64 = 0; break; }
        g_is64 = is64;
        g_acc = 0.0;
    }
}

__device__ __forceinline__ void load_face(const void* faces, long long fe,
                                          int &i0, int &i1, int &i2, int is64)
{
    if (is64) {
        const long long* p = (const long long*)faces + fe * 3;
        i0 = (int)p[0]; i1 = (int)p[1]; i2 = (int)p[2];
    } else {
        const int* p = (const int*)faces + fe * 3;
        i0 = p[0]; i1 = p[1]; i2 = p[2];
    }
}

// ---------------- per-face inverse (area + 1e-12) ----------------
__global__ void k_area(const float* __restrict__ pv, const void* __restrict__ pf,
                       const float* __restrict__ gv, const void* __restrict__ gf)
{
    int t = blockIdx.x * blockDim.x + threadIdx.x;
    if (t >= 2 * NB * NF) return;
    int is64 = g_is64;
    int type = t / (NB * NF);
    int rem  = t - type * (NB * NF);
    int b = rem / NF, f = rem - b * NF;
    const float* verts = (type ? gv : pv) + (size_t)b * NV * 3;
    int i0, i1, i2;
    load_face(type ? gf : pf, (long long)b * NF + f, i0, i1, i2, is64);
    float v0x = verts[i0*3+0], v0y = verts[i0*3+1], v0z = verts[i0*3+2];
    float ax = verts[i1*3+0] - v0x, ay = verts[i1*3+1] - v0y, az = verts[i1*3+2] - v0z;
    float bx = verts[i2*3+0] - v0x, by = verts[i2*3+1] - v0y, bz = verts[i2*3+2] - v0z;
    float cx = ay * bz - az * by;
    float cy = az * bx - ax * bz;
    float cz = ax * by - ay * bx;
    float cn = __fsqrt_rn(cx * cx + cy * cy + cz * cz);
    ((float*)g_invw2)[(b * NF + f) * 2 + type] = __fdiv_rn(1.0f, 0.5f * cn + 1e-12f);
}

// ---------------- gumbel-argmin + fused point generation ----------------
// Inner loop is the R9 configuration verbatim (best measured: 765 us).
#define PROCESS2(bits1, bits2, wva, wvb, fcur) {                                \
    unsigned m1 = (bits1) >> 9, m2 = (bits2) >> 9;                              \
    float yl1 = 2.0f - __uint_as_float(0x3f800000u | m1);                       \
    float yl2 = 2.0f - __uint_as_float(0x3f800000u | m2);                       \
    float c0a = __fmul_rn(yl1, (wva).x), c1a = __fmul_rn(yl1, (wva).y);         \
    float c0b = __fmul_rn(yl2, (wvb).x), c1b = __fmul_rn(yl2, (wvb).y);         \
    if (fminf(c0a, c0b) < bb0f || fminf(c1a, c1b) < bb1f) {                     \
        float lg1 = neglog_u(m1);                                               \
        float lg2 = neglog_u(m2);                                               \
        float t0 = __fmul_rn(lg1, (wva).x);                                     \
        if (t0 < bb0f) { bb0f = t0; bf0 = (fcur); }                             \
        float t1 = __fmul_rn(lg1, (wva).y);                                     \
        if (t1 < bb1f) { bb1f = t1; bf1 = (fcur); }                             \
        float t2 = __fmul_rn(lg2, (wvb).x);                                     \
        if (t2 < bb0f) { bb0f = t2; bf0 = (fcur) + 32; }                        \
        float t3 = __fmul_rn(lg2, (wvb).y);                                     \
        if (t3 < bb1f) { bb1f = t3; bf1 = (fcur) + 32; }                        \
    } }

__global__ void __launch_bounds__(128, 14) k_argmin(
    Keys keys,
    const float* __restrict__ pv, const void* __restrict__ pf,
    const float* __restrict__ gv, const void* __restrict__ gf)
{
    unsigned one = g_one;
    int gw   = blockIdx.x * 4 + (threadIdx.x >> 5);  // global warp = row id
    int lane = threadIdx.x & 31;
    int b = gw >> 12;                                // 4096 rows per batch
    int i = gw & (NS - 1);
    unsigned k0 = keys.k1[b][0], k1 = keys.k1[b][1];
    unsigned ks2 = k0 ^ k1 ^ 0x1BD11BDAu;
    unsigned B1 = ks2 + 1u, B2 = k0 + 2u, B3 = k1 + 3u, B4 = ks2 + 4u, B5 = k0 + 5u;
    const float2* __restrict__ w2 = g_invw2 + b * NF;
    float bb0f = 3.402823466e38f, bb1f = 3.402823466e38f;
    int bf0 = NF, bf1 = NF;
    unsigned eoff = (unsigned)i * (unsigned)NF + k1;

    int f1 = lane;
    unsigned cnt1 = eoff + (unsigned)lane;

    // 215 iterations x 2 chains (215 x 64 = 13760), tail 16
    for (int t = 0; t < 215; t++) {
        unsigned bits1 = tf_fast(k0, k1, ks2, B1, B2, B3, B4, B5, cnt1,       one);
        unsigned bits2 = tf_fast(k0, k1, ks2, B1, B2, B3, B4, B5, cnt1 + 32u, one);
        float2 wa = __ldg(w2 + f1);
        float2 wb = __ldg(w2 + f1 + 32);
        PROCESS2(bits1, bits2, wa, wb, f1)
        f1 += 64;
        MADD(cnt1, 64u);
    }
    if (lane < 16) {                                  // f in [13760, 13776)
        unsigned bits = tf_fast(k0, k1, ks2, B1, B2, B3, B4, B5, cnt1, one);
        float2 wt = __ldg(w2 + f1);
        unsigned m = bits >> 9;
        float yl = 2.0f - __uint_as_float(0x3f800000u | m);
        float c0 = __fmul_rn(yl, wt.x), c1 = __fmul_rn(yl, wt.y);
        if (c0 < bb0f || c1 < bb1f) {
            float lg = neglog_u(m);
            float t0 = __fmul_rn(lg, wt.x);
            if (t0 < bb0f) { bb0f = t0; bf0 = f1; }
            float t1 = __fmul_rn(lg, wt.y);
            if (t1 < bb1f) { bb1f = t1; bf1 = f1; }
        }
    }

#pragma unroll
    for (int off = 16; off > 0; off >>= 1) {
        float ob; int of;
        ob = __shfl_down_sync(0xffffffffu, bb0f, off);
        of = __shfl_down_sync(0xffffffffu, bf0, off);
        if (ob < bb0f || (ob == bb0f && of < bf0)) { bb0f = ob; bf0 = of; }
        ob = __shfl_down_sync(0xffffffffu, bb1f, off);
        of = __shfl_down_sync(0xffffffffu, bf1, off);
        if (ob < bb1f || (ob == bb1f && of < bf1)) { bb1f = ob; bf1 = of; }
    }

    // ---- fused point generation (once per row; lanes 0/1 handle pred/gt) ----
    int wf0 = __shfl_sync(0xffffffffu, bf0, 0);
    int wf1 = __shfl_sync(0xffffffffu, bf1, 0);
    unsigned myb = 0;
    if (lane < 2) {
        // lane 0: u-bits (key2); lane 1: w-bits (key3)
        unsigned kk0 = lane ? keys.k3[b][0] : keys.k2[b][0];
        unsigned kk1 = lane ? keys.k3[b][1] : keys.k2[b][1];
        myb = tf_bits(kk0, kk1, (unsigned)i);
    }
    unsigned bu = __shfl_sync(0xffffffffu, myb, 0);
    unsigned bw = __shfl_sync(0xffffffffu, myb, 1);
    if (lane < 2) {
        int is64 = g_is64;
        int type = lane;
        int f = type ? wf1 : wf0;
        float u = __uint_as_float(0x3f800000u | (bu >> 9)) - 1.0f;
        float w = __uint_as_float(0x3f800000u | (bw >> 9)) - 1.0f;
        float r = __fsqrt_rn(u);
        float a0 = 1.0f - r;
        float a1 = __fmul_rn(r, 1.0f - w);
        float a2 = __fmul_rn(r, w);
        const float* verts = (type ? gv : pv) + (size_t)b * NV * 3;
        int i0, i1, i2;
        load_face(type ? gf : pf, (long long)b * NF + f, i0, i1, i2, is64);
        float* dst = g_pts + ((size_t)(type * NB + b) * NS + i) * 3;
#pragma unroll
        for (int c = 0; c < 3; c++)
            dst[c] = a0 * verts[i0*3+c] + a1 * verts[i1*3+c] + a2 * verts[i2*3+c];
    }
}

// ---------------- brute-force two-way chamfer, TF32-emulated dot ----------------
// pp hoisted out of the j-loop (min is monotone under +pp); -2 folded into the
// tf32-rounded i-point (exact x2 scale). Inner loop: 3 FFMA + 1 FMNMX per pair.
// pp is re-added in k_combine.
__global__ void __launch_bounds__(256) k_chamfer()
{
    int blk   = blockIdx.x;        // 512
    int itile = blk & 3;
    int qt    = (blk >> 2) & 15;
    int seg   = blk >> 6;          // 0..7 : b*2 + dir
    int b = seg >> 1, dir = seg & 1;
    const float* __restrict__ A  = g_pts + (size_t)((dir ? NB : 0) + b) * NS * 3;
    const float* __restrict__ Bq = g_pts + (size_t)((dir ? 0 : NB) + b) * NS * 3;
    int tid = threadIdx.x;

    float npx[4], npy[4], npz[4], mind[4];
#pragma unroll
    for (int r = 0; r < 4; r++) {
        int i = itile * 1024 + r * 256 + tid;
        float px = A[i*3+0], py = A[i*3+1], pz = A[i*3+2];
        npx[r] = -2.0f * tf32r(px);                  // exact scale of tf32 value
        npy[r] = -2.0f * tf32r(py);
        npz[r] = -2.0f * tf32r(pz);
        mind[r] = 3.4e38f;
    }

    __shared__ float4 sq[256];
    {
        int j = qt * 256 + tid;
        float qx = Bq[j*3+0], qy = Bq[j*3+1], qz = Bq[j*3+2];
        sq[tid] = make_float4(tf32r(qx), tf32r(qy), tf32r(qz),
                              qx*qx + qy*qy + qz*qz);
    }
    __syncthreads();
#pragma unroll 4
    for (int k = 0; k < 256; k++) {
        float4 q = sq[k];
#pragma unroll
        for (int r = 0; r < 4; r++) {
            float d = __fmaf_rn(q.z, npz[r], q.w);
            d = __fmaf_rn(q.y, npy[r], d);
            d = __fmaf_rn(q.x, npx[r], d);
            mind[r] = fminf(mind[r], d);
        }
    }
#pragma unroll
    for (int r = 0; r < 4; r++) {
        int i = itile * 1024 + r * 256 + tid;
        g_pmin[(seg * 16 + qt) * NS + i] = mind[r];
    }
}

__global__ void __launch_bounds__(256) k_combine()
{
    int t = blockIdx.x * 256 + threadIdx.x;   // 0..32767
    int seg = t >> 12, i = t & (NS - 1);
    int b = seg >> 1, dir = seg & 1;
    const float* __restrict__ A = g_pts + (size_t)((dir ? NB : 0) + b) * NS * 3;
    float px = A[i*3+0], py = A[i*3+1], pz = A[i*3+2];
    float pp = px*px + py*py + pz*pz;         // exact f32, as before
    const float* pm = g_pmin + seg * 16 * NS + i;
    float m = 3.4e38f;
#pragma unroll
    for (int q = 0; q < 16; q++)
        m = fminf(m, pm[q * NS]);
    __shared__ double sd[256];
    sd[threadIdx.x] = (double)(m + pp);
    __syncthreads();
    for (int off = 128; off > 0; off >>= 1) {
        if (threadIdx.x < off) sd[threadIdx.x] += sd[threadIdx.x + off];
        __syncthreads();
    }
    if (threadIdx.x == 0) atomicAdd(&g_acc, sd[0]);
}

__global__ void k_final(float* out)
{
    out[0] = (float)(g_acc * (1.0 / 16384.0));   // mean(d1)+mean(d2), CHAMFER_W=1
}

// ---------------- launch ----------------
extern "C" void kernel_launch(void* const* d_in, const int* in_sizes, int n_in,
                              void* d_out, int out_size)
{
    const float* pv = (const float*)d_in[0];
    const void*  pf = (const void*)d_in[1];
    const float* gv = (const float*)d_in[2];
    const void*  gf = (const void*)d_in[3];

    // Partitionable (foldlike) split: key_i = threefry(key, (0, i)), both
    // outputs form the new key. key(42) = (0, 42).
    Keys keys;
    for (int b = 0; b < 4; b++) {
        unsigned kb0, kb1;
        tf2x32(0u, 42u, 0u, (unsigned)b, kb0, kb1);
        tf2x32(kb0, kb1, 0u, 0u, keys.k1[b][0], keys.k1[b][1]);
        tf2x32(kb0, kb1, 0u, 1u, keys.k2[b][0], keys.k2[b][1]);
        tf2x32(kb0, kb1, 0u, 2u, keys.k3[b][0], keys.k3[b][1]);
    }

    k_detect<<<1, 32>>>((const int*)pf);
    k_area<<<(2 * NB * NF + 255) / 256, 256>>>(pv, pf, gv, gf);
    k_argmin<<<NB * NS / 4, 128>>>(keys, pv, pf, gv, gf);
    k_chamfer<<<512, 256>>>();
    k_combine<<<128, 256>>>();
    k_final<<<1, 1>>>((float*)d_out);
}

// round 15
// speedup vs baseline: 1.0853x; 1.0046x over previous
#include <cuda_runtime.h>

#define NB 4
#define NV 6890
#define NF 13776
#define NS 4096

struct Keys {
    unsigned k1[NB][2];
    unsigned k2[NB][2];
    unsigned k3[NB][2];
};

__device__ float2   g_invw2[NB * NF];        // (wpred, wgt) interleaved
__device__ float    g_pts [2 * NB * NS * 3];
__device__ float    g_pmin[8 * 32 * NS];     // [seg][qtile][i]  (pp-hoisted)
__device__ double   g_acc;
__device__ int      g_is64;
__device__ unsigned g_one = 1;               // opaque 1: forces IMAD, not IADD3

// ---------------- threefry2x32 (20 rounds), exact JAX semantics ----------------
__host__ __device__ __forceinline__ void tf2x32(unsigned k0, unsigned k1,
                                                unsigned c0, unsigned c1,
                                                unsigned &o0, unsigned &o1)
{
    unsigned ks2 = k0 ^ k1 ^ 0x1BD11BDAu;
    unsigned x0 = c0 + k0;
    unsigned x1 = c1 + k1;
#if defined(__CUDA_ARCH__)
#define TF_ROTL(x, r) __funnelshift_l((x), (x), (r))
#else
#define TF_ROTL(x, r) (((x) << (r)) | ((x) >> (32 - (r))))
#endif
#define TF_RND(r) { x0 += x1; x1 = TF_ROTL(x1, r); x1 ^= x0; }
    TF_RND(13) TF_RND(15) TF_RND(26) TF_RND(6)
    x0 += k1;  x1 += ks2 + 1u;
    TF_RND(17) TF_RND(29) TF_RND(16) TF_RND(24)
    x0 += ks2; x1 += k0 + 2u;
    TF_RND(13) TF_RND(15) TF_RND(26) TF_RND(6)
    x0 += k0;  x1 += k1 + 3u;
    TF_RND(17) TF_RND(29) TF_RND(16) TF_RND(24)
    x0 += k1;  x1 += ks2 + 4u;
    TF_RND(13) TF_RND(15) TF_RND(26) TF_RND(6)
    x0 += ks2; x1 += k0 + 5u;
#undef TF_RND
#undef TF_ROTL
    o0 = x0; o1 = x1;
}

// partitionable random_bits (32-bit): counter = (0, flat_index), out = x0 ^ x1
__host__ __device__ __forceinline__ unsigned tf_bits(unsigned k0, unsigned k1,
                                                     unsigned e)
{
    unsigned o0, o1;
    tf2x32(k0, k1, 0u, e, o0, o1);
    return o0 ^ o1;
}

// Pipe-balanced threefry for c0=0: integer adds forced onto the fma pipe as
// IMAD (mad.lo with opaque one); SHF/LOP3 stay on the alu pipe.
// Caller passes cnt = e + k1 (pre-added).
#define MADD(d, a) asm("mad.lo.u32 %0, %1, %2, %0;" : "+r"(d) : "r"(a), "r"(one))

__device__ __forceinline__ unsigned tf_fast(unsigned k0, unsigned k1, unsigned ks2,
                                            unsigned B1, unsigned B2, unsigned B3,
                                            unsigned B4, unsigned B5,
                                            unsigned cnt, unsigned one)
{
    unsigned x0 = k0;        // 0 + k0
    unsigned x1 = cnt;       // e + k1 (pre-added by caller)
#define TFR(r) { MADD(x0, x1); x1 = __funnelshift_l(x1, x1, r) ^ x0; }
    TFR(13) TFR(15) TFR(26) TFR(6)
    MADD(x0, k1);  MADD(x1, B1);
    TFR(17) TFR(29) TFR(16) TFR(24)
    MADD(x0, ks2); MADD(x1, B2);
    TFR(13) TFR(15) TFR(26) TFR(6)
    MADD(x0, k0);  MADD(x1, B3);
    TFR(17) TFR(29) TFR(16) TFR(24)
    MADD(x0, k1);  MADD(x1, B4);
    TFR(13) TFR(15) TFR(26) TFR(6)
    MADD(x0, ks2); MADD(x1, B5);
#undef TFR
    return x0 ^ x1;
}

// -------- accurate -log(u'), u' = (m==0 ? tiny : m*2^-23), ~1-2 ulp relative ----
__device__ __forceinline__ float neglog_u(unsigned m)  // m = bits >> 9
{
    float u;
    if (m == 0u) u = 1.17549435e-38f;                         // finfo(f32).tiny
    else         u = __uint_as_float(0x3f800000u | m) - 1.0f; // exact
    unsigned bi = __float_as_uint(u);
    int e = (int)(bi >> 23) - 126;                            // u = x0*2^e, x0 in [0.5,1)
    float x = __uint_as_float((bi & 0x007fffffu) | (126u << 23));
    if (x < 0.70710678f) { x = x + x; e -= 1; }               // x in [0.7071, 1.4142)
    float s = __fdiv_rn(x - 1.0f, x + 1.0f);                  // x-1 exact (Sterbenz)
    float t = s * s;
    float P = __fmaf_rn(t, __fmaf_rn(t, __fmaf_rn(t, 0.11111111f, 0.14285715f),
                                     0.2f), 0.33333334f);
    float q = s + s;
    float lnx = __fmaf_rn(q * t, P, q);                       // ln x = 2s + 2s*t*P
    float kf = (float)e;
    float r = __fmaf_rn(kf, -2.12194440e-4f, lnx);            // ln2_lo
    r = __fmaf_rn(kf, 0.693359375f, r);                       // ln2_hi
    return -r;
}

// ---------------- tf32 rounding (RNA, matches cvt.rna.tf32.f32) ----------------
__device__ __forceinline__ float tf32r(float x)
{
    unsigned b = __float_as_uint(x);
    b = (b + 0x1000u) & 0xffffe000u;
    return __uint_as_float(b);
}

// ---------------- faces dtype detection (int32 vs int64) + zero ----------------
__global__ void k_detect(const int* __restrict__ pf32)
{
    if (threadIdx.x == 0) {
        int is64 = 1;
        for (int i = 0; i < 64; i++)
            if (pf32[2 * i + 1] != 0) { is64 = 0; break; }
        g_is64 = is64;
        g_acc = 0.0;
    }
}

__device__ __forceinline__ void load_face(const void* faces, long long fe,
                                          int &i0, int &i1, int &i2, int is64)
{
    if (is64) {
        const long long* p = (const long long*)faces + fe * 3;
        i0 = (int)p[0]; i1 = (int)p[1]; i2 = (int)p[2];
    } else {
        const int* p = (const int*)faces + fe * 3;
        i0 = p[0]; i1 = p[1]; i2 = p[2];
    }
}

// ---------------- per-face inverse (area + 1e-12) ----------------
__global__ void k_area(const float* __restrict__ pv, const void* __restrict__ pf,
                       const float* __restrict__ gv, const void* __restrict__ gf)
{
    int t = blockIdx.x * blockDim.x + threadIdx.x;
    if (t >= 2 * NB * NF) return;
    int is64 = g_is64;
    int type = t / (NB * NF);
    int rem  = t - type * (NB * NF);
    int b = rem / NF, f = rem - b * NF;
    const float* verts = (type ? gv : pv) + (size_t)b * NV * 3;
    int i0, i1, i2;
    load_face(type ? gf : pf, (long long)b * NF + f, i0, i1, i2, is64);
    float v0x = verts[i0*3+0], v0y = verts[i0*3+1], v0z = verts[i0*3+2];
    float ax = verts[i1*3+0] - v0x, ay = verts[i1*3+1] - v0y, az = verts[i1*3+2] - v0z;
    float bx = verts[i2*3+0] - v0x, by = verts[i2*3+1] - v0y, bz = verts[i2*3+2] - v0z;
    float cx = ay * bz - az * by;
    float cy = az * bx - ax * bz;
    float cz = ax * by - ay * bx;
    float cn = __fsqrt_rn(cx * cx + cy * cy + cz * cz);
    ((float*)g_invw2)[(b * NF + f) * 2 + type] = __fdiv_rn(1.0f, 0.5f * cn + 1e-12f);
}

// ---------------- gumbel-argmin + fused point generation ----------------
// Inner loop is the R9 configuration verbatim (best measured: 765 us).
#define PROCESS2(bits1, bits2, wva, wvb, fcur) {                                \
    unsigned m1 = (bits1) >> 9, m2 = (bits2) >> 9;                              \
    float yl1 = 2.0f - __uint_as_float(0x3f800000u | m1);                       \
    float yl2 = 2.0f - __uint_as_float(0x3f800000u | m2);                       \
    float c0a = __fmul_rn(yl1, (wva).x), c1a = __fmul_rn(yl1, (wva).y);         \
    float c0b = __fmul_rn(yl2, (wvb).x), c1b = __fmul_rn(yl2, (wvb).y);         \
    if (fminf(c0a, c0b) < bb0f || fminf(c1a, c1b) < bb1f) {                     \
        float lg1 = neglog_u(m1);                                               \
        float lg2 = neglog_u(m2);                                               \
        float t0 = __fmul_rn(lg1, (wva).x);                                     \
        if (t0 < bb0f) { bb0f = t0; bf0 = (fcur); }                             \
        float t1 = __fmul_rn(lg1, (wva).y);                                     \
        if (t1 < bb1f) { bb1f = t1; bf1 = (fcur); }                             \
        float t2 = __fmul_rn(lg2, (wvb).x);                                     \
        if (t2 < bb0f) { bb0f = t2; bf0 = (fcur) + 32; }                        \
        float t3 = __fmul_rn(lg2, (wvb).y);                                     \
        if (t3 < bb1f) { bb1f = t3; bf1 = (fcur) + 32; }                        \
    } }

__global__ void __launch_bounds__(128, 14) k_argmin(
    Keys keys,
    const float* __restrict__ pv, const void* __restrict__ pf,
    const float* __restrict__ gv, const void* __restrict__ gf)
{
    unsigned one = g_one;
    int gw   = blockIdx.x * 4 + (threadIdx.x >> 5);  // global warp = row id
    int lane = threadIdx.x & 31;
    int b = gw >> 12;                                // 4096 rows per batch
    int i = gw & (NS - 1);
    unsigned k0 = keys.k1[b][0], k1 = keys.k1[b][1];
    unsigned ks2 = k0 ^ k1 ^ 0x1BD11BDAu;
    unsigned B1 = ks2 + 1u, B2 = k0 + 2u, B3 = k1 + 3u, B4 = ks2 + 4u, B5 = k0 + 5u;
    const float2* __restrict__ w2 = g_invw2 + b * NF;
    float bb0f = 3.402823466e38f, bb1f = 3.402823466e38f;
    int bf0 = NF, bf1 = NF;
    unsigned eoff = (unsigned)i * (unsigned)NF + k1;

    int f1 = lane;
    unsigned cnt1 = eoff + (unsigned)lane;

    // 215 iterations x 2 chains (215 x 64 = 13760), tail 16
    for (int t = 0; t < 215; t++) {
        unsigned bits1 = tf_fast(k0, k1, ks2, B1, B2, B3, B4, B5, cnt1,       one);
        unsigned bits2 = tf_fast(k0, k1, ks2, B1, B2, B3, B4, B5, cnt1 + 32u, one);
        float2 wa = __ldg(w2 + f1);
        float2 wb = __ldg(w2 + f1 + 32);
        PROCESS2(bits1, bits2, wa, wb, f1)
        f1 += 64;
        MADD(cnt1, 64u);
    }
    if (lane < 16) {                                  // f in [13760, 13776)
        unsigned bits = tf_fast(k0, k1, ks2, B1, B2, B3, B4, B5, cnt1, one);
        float2 wt = __ldg(w2 + f1);
        unsigned m = bits >> 9;
        float yl = 2.0f - __uint_as_float(0x3f800000u | m);
        float c0 = __fmul_rn(yl, wt.x), c1 = __fmul_rn(yl, wt.y);
        if (c0 < bb0f || c1 < bb1f) {
            float lg = neglog_u(m);
            float t0 = __fmul_rn(lg, wt.x);
            if (t0 < bb0f) { bb0f = t0; bf0 = f1; }
            float t1 = __fmul_rn(lg, wt.y);
            if (t1 < bb1f) { bb1f = t1; bf1 = f1; }
        }
    }

#pragma unroll
    for (int off = 16; off > 0; off >>= 1) {
        float ob; int of;
        ob = __shfl_down_sync(0xffffffffu, bb0f, off);
        of = __shfl_down_sync(0xffffffffu, bf0, off);
        if (ob < bb0f || (ob == bb0f && of < bf0)) { bb0f = ob; bf0 = of; }
        ob = __shfl_down_sync(0xffffffffu, bb1f, off);
        of = __shfl_down_sync(0xffffffffu, bf1, off);
        if (ob < bb1f || (ob == bb1f && of < bf1)) { bb1f = ob; bf1 = of; }
    }

    // ---- fused point generation (once per row; lanes 0/1 handle pred/gt) ----
    int wf0 = __shfl_sync(0xffffffffu, bf0, 0);
    int wf1 = __shfl_sync(0xffffffffu, bf1, 0);
    unsigned myb = 0;
    if (lane < 2) {
        // lane 0: u-bits (key2); lane 1: w-bits (key3)
        unsigned kk0 = lane ? keys.k3[b][0] : keys.k2[b][0];
        unsigned kk1 = lane ? keys.k3[b][1] : keys.k2[b][1];
        myb = tf_bits(kk0, kk1, (unsigned)i);
    }
    unsigned bu = __shfl_sync(0xffffffffu, myb, 0);
    unsigned bw = __shfl_sync(0xffffffffu, myb, 1);
    if (lane < 2) {
        int is64 = g_is64;
        int type = lane;
        int f = type ? wf1 : wf0;
        float u = __uint_as_float(0x3f800000u | (bu >> 9)) - 1.0f;
        float w = __uint_as_float(0x3f800000u | (bw >> 9)) - 1.0f;
        float r = __fsqrt_rn(u);
        float a0 = 1.0f - r;
        float a1 = __fmul_rn(r, 1.0f - w);
        float a2 = __fmul_rn(r, w);
        const float* verts = (type ? gv : pv) + (size_t)b * NV * 3;
        int i0, i1, i2;
        load_face(type ? gf : pf, (long long)b * NF + f, i0, i1, i2, is64);
        float* dst = g_pts + ((size_t)(type * NB + b) * NS + i) * 3;
#pragma unroll
        for (int c = 0; c < 3; c++)
            dst[c] = a0 * verts[i0*3+c] + a1 * verts[i1*3+c] + a2 * verts[i2*3+c];
    }
}

// ---------------- brute-force two-way chamfer, TF32-emulated dot ----------------
// pp hoisted (re-added in k_combine); -2 folded into tf32-rounded i-point.
// 1024 blocks: 8 segs x 4 i-tiles x 32 q-tiles of 128 -> ~6 CTAs/SM.
__global__ void __launch_bounds__(256) k_chamfer()
{
    int blk   = blockIdx.x;        // 1024
    int itile = blk & 3;
    int qt    = (blk >> 2) & 31;
    int seg   = blk >> 7;          // 0..7 : b*2 + dir
    int b = seg >> 1, dir = seg & 1;
    const float* __restrict__ A  = g_pts + (size_t)((dir ? NB : 0) + b) * NS * 3;
    const float* __restrict__ Bq = g_pts + (size_t)((dir ? 0 : NB) + b) * NS * 3;
    int tid = threadIdx.x;

    float npx[4], npy[4], npz[4], mind[4];
#pragma unroll
    for (int r = 0; r < 4; r++) {
        int i = itile * 1024 + r * 256 + tid;
        float px = A[i*3+0], py = A[i*3+1], pz = A[i*3+2];
        npx[r] = -2.0f * tf32r(px);                  // exact scale of tf32 value
        npy[r] = -2.0f * tf32r(py);
        npz[r] = -2.0f * tf32r(pz);
        mind[r] = 3.4e38f;
    }

    __shared__ float4 sq[128];
    if (tid < 128) {
        int j = qt * 128 + tid;
        float qx = Bq[j*3+0], qy = Bq[j*3+1], qz = Bq[j*3+2];
        sq[tid] = make_float4(tf32r(qx), tf32r(qy), tf32r(qz),
                              qx*qx + qy*qy + qz*qz);
    }
    __syncthreads();
#pragma unroll 4
    for (int k = 0; k < 128; k++) {
        float4 q = sq[k];
#pragma unroll
        for (int r = 0; r < 4; r++) {
            float d = __fmaf_rn(q.z, npz[r], q.w);
            d = __fmaf_rn(q.y, npy[r], d);
            d = __fmaf_rn(q.x, npx[r], d);
            mind[r] = fminf(mind[r], d);
        }
    }
#pragma unroll
    for (int r = 0; r < 4; r++) {
        int i = itile * 1024 + r * 256 + tid;
        g_pmin[(seg * 32 + qt) * NS + i] = mind[r];
    }
}

__global__ void __launch_bounds__(256) k_combine()
{
    int t = blockIdx.x * 256 + threadIdx.x;   // 0..32767
    int seg = t >> 12, i = t & (NS - 1);
    int b = seg >> 1, dir = seg & 1;
    const float* __restrict__ A = g_pts + (size_t)((dir ? NB : 0) + b) * NS * 3;
    float px = A[i*3+0], py = A[i*3+1], pz = A[i*3+2];
    float pp = px*px + py*py + pz*pz;         // exact f32, as before
    const float* pm = g_pmin + seg * 32 * NS + i;
    float m = 3.4e38f;
#pragma unroll
    for (int q = 0; q < 32; q++)
        m = fminf(m, pm[q * NS]);
    __shared__ double sd[256];
    sd[threadIdx.x] = (double)(m + pp);
    __syncthreads();
    for (int off = 128; off > 0; off >>= 1) {
        if (threadIdx.x < off) sd[threadIdx.x] += sd[threadIdx.x + off];
        __syncthreads();
    }
    if (threadIdx.x == 0) atomicAdd(&g_acc, sd[0]);
}

__global__ void k_final(float* out)
{
    out[0] = (float)(g_acc * (1.0 / 16384.0));   // mean(d1)+mean(d2), CHAMFER_W=1
}

// ---------------- launch ----------------
extern "C" void kernel_launch(void* const* d_in, const int* in_sizes, int n_in,
                              void* d_out, int out_size)
{
    const float* pv = (const float*)d_in[0];
    const void*  pf = (const void*)d_in[1];
    const float* gv = (const float*)d_in[2];
    const void*  gf = (const void*)d_in[3];

    // Partitionable (foldlike) split: key_i = threefry(key, (0, i)), both
    // outputs form the new key. key(42) = (0, 42).
    Keys keys;
    for (int b = 0; b < 4; b++) {
        unsigned kb0, kb1;
        tf2x32(0u, 42u, 0u, (unsigned)b, kb0, kb1);
        tf2x32(kb0, kb1, 0u, 0u, keys.k1[b][0], keys.k1[b][1]);
        tf2x32(kb0, kb1, 0u, 1u, keys.k2[b][0], keys.k2[b][1]);
        tf2x32(kb0, kb1, 0u, 2u, keys.k3[b][0], keys.k3[b][1]);
    }

    k_detect<<<1, 32>>>((const int*)pf);
    k_area<<<(2 * NB * NF + 255) / 256, 256>>>(pv, pf, gv, gf);
    k_argmin<<<NB * NS / 4, 128>>>(keys, pv, pf, gv, gf);
    k_chamfer<<<1024, 256>>>();
    k_combine<<<128, 256>>>();
    k_final<<<1, 1>>>((float*)d_out);
}

// round 16
// speedup vs baseline: 1.0881x; 1.0026x over previous
#include <cuda_runtime.h>

#define NB 4
#define NV 6890
#define NF 13776
#define NS 4096

struct Keys {
    unsigned k1[NB][2];
    unsigned k2[NB][2];
    unsigned k3[NB][2];
};

__device__ float2   g_invw2[NB * NF];        // (wpred, wgt) interleaved
__device__ float    g_pts [2 * NB * NS * 3];
__device__ float    g_pmin[8 * 32 * NS];     // [seg][qtile][i]  (pp-hoisted)
__device__ double   g_acc;
__device__ unsigned g_cnt;
__device__ int      g_is64;
__device__ unsigned g_one = 1;               // opaque 1: forces IMAD, not IADD3

// ---------------- threefry2x32 (20 rounds), exact JAX semantics ----------------
__host__ __device__ __forceinline__ void tf2x32(unsigned k0, unsigned k1,
                                                unsigned c0, unsigned c1,
                                                unsigned &o0, unsigned &o1)
{
    unsigned ks2 = k0 ^ k1 ^ 0x1BD11BDAu;
    unsigned x0 = c0 + k0;
    unsigned x1 = c1 + k1;
#if defined(__CUDA_ARCH__)
#define TF_ROTL(x, r) __funnelshift_l((x), (x), (r))
#else
#define TF_ROTL(x, r) (((x) << (r)) | ((x) >> (32 - (r))))
#endif
#define TF_RND(r) { x0 += x1; x1 = TF_ROTL(x1, r); x1 ^= x0; }
    TF_RND(13) TF_RND(15) TF_RND(26) TF_RND(6)
    x0 += k1;  x1 += ks2 + 1u;
    TF_RND(17) TF_RND(29) TF_RND(16) TF_RND(24)
    x0 += ks2; x1 += k0 + 2u;
    TF_RND(13) TF_RND(15) TF_RND(26) TF_RND(6)
    x0 += k0;  x1 += k1 + 3u;
    TF_RND(17) TF_RND(29) TF_RND(16) TF_RND(24)
    x0 += k1;  x1 += ks2 + 4u;
    TF_RND(13) TF_RND(15) TF_RND(26) TF_RND(6)
    x0 += ks2; x1 += k0 + 5u;
#undef TF_RND
#undef TF_ROTL
    o0 = x0; o1 = x1;
}

// partitionable random_bits (32-bit): counter = (0, flat_index), out = x0 ^ x1
__host__ __device__ __forceinline__ unsigned tf_bits(unsigned k0, unsigned k1,
                                                     unsigned e)
{
    unsigned o0, o1;
    tf2x32(k0, k1, 0u, e, o0, o1);
    return o0 ^ o1;
}

// Pipe-balanced threefry for c0=0: integer adds forced onto the fma pipe as
// IMAD (mad.lo with opaque one); SHF/LOP3 stay on the alu pipe.
// Caller passes cnt = e + k1 (pre-added).
#define MADD(d, a) asm("mad.lo.u32 %0, %1, %2, %0;" : "+r"(d) : "r"(a), "r"(one))

__device__ __forceinline__ unsigned tf_fast(unsigned k0, unsigned k1, unsigned ks2,
                                            unsigned B1, unsigned B2, unsigned B3,
                                            unsigned B4, unsigned B5,
                                            unsigned cnt, unsigned one)
{
    unsigned x0 = k0;        // 0 + k0
    unsigned x1 = cnt;       // e + k1 (pre-added by caller)
#define TFR(r) { MADD(x0, x1); x1 = __funnelshift_l(x1, x1, r) ^ x0; }
    TFR(13) TFR(15) TFR(26) TFR(6)
    MADD(x0, k1);  MADD(x1, B1);
    TFR(17) TFR(29) TFR(16) TFR(24)
    MADD(x0, ks2); MADD(x1, B2);
    TFR(13) TFR(15) TFR(26) TFR(6)
    MADD(x0, k0);  MADD(x1, B3);
    TFR(17) TFR(29) TFR(16) TFR(24)
    MADD(x0, k1);  MADD(x1, B4);
    TFR(13) TFR(15) TFR(26) TFR(6)
    MADD(x0, ks2); MADD(x1, B5);
#undef TFR
    return x0 ^ x1;
}

// -------- accurate -log(u'), u' = (m==0 ? tiny : m*2^-23), ~1-2 ulp relative ----
__device__ __forceinline__ float neglog_u(unsigned m)  // m = bits >> 9
{
    float u;
    if (m == 0u) u = 1.17549435e-38f;                         // finfo(f32).tiny
    else         u = __uint_as_float(0x3f800000u | m) - 1.0f; // exact
    unsigned bi = __float_as_uint(u);
    int e = (int)(bi >> 23) - 126;                            // u = x0*2^e, x0 in [0.5,1)
    float x = __uint_as_float((bi & 0x007fffffu) | (126u << 23));
    if (x < 0.70710678f) { x = x + x; e -= 1; }               // x in [0.7071, 1.4142)
    float s = __fdiv_rn(x - 1.0f, x + 1.0f);                  // x-1 exact (Sterbenz)
    float t = s * s;
    float P = __fmaf_rn(t, __fmaf_rn(t, __fmaf_rn(t, 0.11111111f, 0.14285715f),
                                     0.2f), 0.33333334f);
    float q = s + s;
    float lnx = __fmaf_rn(q * t, P, q);                       // ln x = 2s + 2s*t*P
    float kf = (float)e;
    float r = __fmaf_rn(kf, -2.12194440e-4f, lnx);            // ln2_lo
    r = __fmaf_rn(kf, 0.693359375f, r);                       // ln2_hi
    return -r;
}

// ---------------- tf32 rounding (RNA, matches cvt.rna.tf32.f32) ----------------
__device__ __forceinline__ float tf32r(float x)
{
    unsigned b = __float_as_uint(x);
    b = (b + 0x1000u) & 0xffffe000u;
    return __uint_as_float(b);
}

__device__ __forceinline__ void load_face(const void* faces, long long fe,
                                          int &i0, int &i1, int &i2, int is64)
{
    if (is64) {
        const long long* p = (const long long*)faces + fe * 3;
        i0 = (int)p[0]; i1 = (int)p[1]; i2 = (int)p[2];
    } else {
        const int* p = (const int*)faces + fe * 3;
        i0 = p[0]; i1 = p[1]; i2 = p[2];
    }
}

// ---------------- per-face inverse (area + 1e-12), fused dtype-detect ----------------
__global__ void k_area(const float* __restrict__ pv, const void* __restrict__ pf,
                       const float* __restrict__ gv, const void* __restrict__ gf)
{
    __shared__ int s_is64;
    if (threadIdx.x == 0) {
        const int* pf32 = (const int*)pf;
        int is64 = 1;
        for (int i = 0; i < 64; i++)
            if (pf32[2 * i + 1] != 0) { is64 = 0; break; }
        s_is64 = is64;
        if (blockIdx.x == 0) {
            g_is64 = is64;
            g_acc = 0.0;
            g_cnt = 0u;
        }
    }
    __syncthreads();
    int is64 = s_is64;
    int t = blockIdx.x * blockDim.x + threadIdx.x;
    if (t >= 2 * NB * NF) return;
    int type = t / (NB * NF);
    int rem  = t - type * (NB * NF);
    int b = rem / NF, f = rem - b * NF;
    const float* verts = (type ? gv : pv) + (size_t)b * NV * 3;
    int i0, i1, i2;
    load_face(type ? gf : pf, (long long)b * NF + f, i0, i1, i2, is64);
    float v0x = verts[i0*3+0], v0y = verts[i0*3+1], v0z = verts[i0*3+2];
    float ax = verts[i1*3+0] - v0x, ay = verts[i1*3+1] - v0y, az = verts[i1*3+2] - v0z;
    float bx = verts[i2*3+0] - v0x, by = verts[i2*3+1] - v0y, bz = verts[i2*3+2] - v0z;
    float cx = ay * bz - az * by;
    float cy = az * bx - ax * bz;
    float cz = ax * by - ay * bx;
    float cn = __fsqrt_rn(cx * cx + cy * cy + cz * cz);
    ((float*)g_invw2)[(b * NF + f) * 2 + type] = __fdiv_rn(1.0f, 0.5f * cn + 1e-12f);
}

// ---------------- gumbel-argmin + fused point generation ----------------
// Inner loop is the R9 configuration verbatim (best measured: 765 us).
#define PROCESS2(bits1, bits2, wva, wvb, fcur) {                                \
    unsigned m1 = (bits1) >> 9, m2 = (bits2) >> 9;                              \
    float yl1 = 2.0f - __uint_as_float(0x3f800000u | m1);                       \
    float yl2 = 2.0f - __uint_as_float(0x3f800000u | m2);                       \
    float c0a = __fmul_rn(yl1, (wva).x), c1a = __fmul_rn(yl1, (wva).y);         \
    float c0b = __fmul_rn(yl2, (wvb).x), c1b = __fmul_rn(yl2, (wvb).y);         \
    if (fminf(c0a, c0b) < bb0f || fminf(c1a, c1b) < bb1f) {                     \
        float lg1 = neglog_u(m1);                                               \
        float lg2 = neglog_u(m2);                                               \
        float t0 = __fmul_rn(lg1, (wva).x);                                     \
        if (t0 < bb0f) { bb0f = t0; bf0 = (fcur); }                             \
        float t1 = __fmul_rn(lg1, (wva).y);                                     \
        if (t1 < bb1f) { bb1f = t1; bf1 = (fcur); }                             \
        float t2 = __fmul_rn(lg2, (wvb).x);                                     \
        if (t2 < bb0f) { bb0f = t2; bf0 = (fcur) + 32; }                        \
        float t3 = __fmul_rn(lg2, (wvb).y);                                     \
        if (t3 < bb1f) { bb1f = t3; bf1 = (fcur) + 32; }                        \
    } }

__global__ void __launch_bounds__(128, 14) k_argmin(
    Keys keys,
    const float* __restrict__ pv, const void* __restrict__ pf,
    const float* __restrict__ gv, const void* __restrict__ gf)
{
    unsigned one = g_one;
    int gw   = blockIdx.x * 4 + (threadIdx.x >> 5);  // global warp = row id
    int lane = threadIdx.x & 31;
    int b = gw >> 12;                                // 4096 rows per batch
    int i = gw & (NS - 1);
    unsigned k0 = keys.k1[b][0], k1 = keys.k1[b][1];
    unsigned ks2 = k0 ^ k1 ^ 0x1BD11BDAu;
    unsigned B1 = ks2 + 1u, B2 = k0 + 2u, B3 = k1 + 3u, B4 = ks2 + 4u, B5 = k0 + 5u;
    const float2* __restrict__ w2 = g_invw2 + b * NF;
    float bb0f = 3.402823466e38f, bb1f = 3.402823466e38f;
    int bf0 = NF, bf1 = NF;
    unsigned eoff = (unsigned)i * (unsigned)NF + k1;

    int f1 = lane;
    unsigned cnt1 = eoff + (unsigned)lane;

    // 215 iterations x 2 chains (215 x 64 = 13760), tail 16
    for (int t = 0; t < 215; t++) {
        unsigned bits1 = tf_fast(k0, k1, ks2, B1, B2, B3, B4, B5, cnt1,       one);
        unsigned bits2 = tf_fast(k0, k1, ks2, B1, B2, B3, B4, B5, cnt1 + 32u, one);
        float2 wa = __ldg(w2 + f1);
        float2 wb = __ldg(w2 + f1 + 32);
        PROCESS2(bits1, bits2, wa, wb, f1)
        f1 += 64;
        MADD(cnt1, 64u);
    }
    if (lane < 16) {                                  // f in [13760, 13776)
        unsigned bits = tf_fast(k0, k1, ks2, B1, B2, B3, B4, B5, cnt1, one);
        float2 wt = __ldg(w2 + f1);
        unsigned m = bits >> 9;
        float yl = 2.0f - __uint_as_float(0x3f800000u | m);
        float c0 = __fmul_rn(yl, wt.x), c1 = __fmul_rn(yl, wt.y);
        if (c0 < bb0f || c1 < bb1f) {
            float lg = neglog_u(m);
            float t0 = __fmul_rn(lg, wt.x);
            if (t0 < bb0f) { bb0f = t0; bf0 = f1; }
            float t1 = __fmul_rn(lg, wt.y);
            if (t1 < bb1f) { bb1f = t1; bf1 = f1; }
        }
    }

#pragma unroll
    for (int off = 16; off > 0; off >>= 1) {
        float ob; int of;
        ob = __shfl_down_sync(0xffffffffu, bb0f, off);
        of = __shfl_down_sync(0xffffffffu, bf0, off);
        if (ob < bb0f || (ob == bb0f && of < bf0)) { bb0f = ob; bf0 = of; }
        ob = __shfl_down_sync(0xffffffffu, bb1f, off);
        of = __shfl_down_sync(0xffffffffu, bf1, off);
        if (ob < bb1f || (ob == bb1f && of < bf1)) { bb1f = ob; bf1 = of; }
    }

    // ---- fused point generation (once per row; lanes 0/1 handle pred/gt) ----
    int wf0 = __shfl_sync(0xffffffffu, bf0, 0);
    int wf1 = __shfl_sync(0xffffffffu, bf1, 0);
    unsigned myb = 0;
    if (lane < 2) {
        // lane 0: u-bits (key2); lane 1: w-bits (key3)
        unsigned kk0 = lane ? keys.k3[b][0] : keys.k2[b][0];
        unsigned kk1 = lane ? keys.k3[b][1] : keys.k2[b][1];
        myb = tf_bits(kk0, kk1, (unsigned)i);
    }
    unsigned bu = __shfl_sync(0xffffffffu, myb, 0);
    unsigned bw = __shfl_sync(0xffffffffu, myb, 1);
    if (lane < 2) {
        int is64 = g_is64;
        int type = lane;
        int f = type ? wf1 : wf0;
        float u = __uint_as_float(0x3f800000u | (bu >> 9)) - 1.0f;
        float w = __uint_as_float(0x3f800000u | (bw >> 9)) - 1.0f;
        float r = __fsqrt_rn(u);
        float a0 = 1.0f - r;
        float a1 = __fmul_rn(r, 1.0f - w);
        float a2 = __fmul_rn(r, w);
        const float* verts = (type ? gv : pv) + (size_t)b * NV * 3;
        int i0, i1, i2;
        load_face(type ? gf : pf, (long long)b * NF + f, i0, i1, i2, is64);
        float* dst = g_pts + ((size_t)(type * NB + b) * NS + i) * 3;
#pragma unroll
        for (int c = 0; c < 3; c++)
            dst[c] = a0 * verts[i0*3+c] + a1 * verts[i1*3+c] + a2 * verts[i2*3+c];
    }
}

// ---------------- brute-force two-way chamfer, TF32-emulated dot ----------------
// pp hoisted (re-added in k_combine); -2 folded into tf32-rounded i-point.
// 1024 blocks: 8 segs x 4 i-tiles x 32 q-tiles of 128 -> ~6 CTAs/SM.
__global__ void __launch_bounds__(256) k_chamfer()
{
    int blk   = blockIdx.x;        // 1024
    int itile = blk & 3;
    int qt    = (blk >> 2) & 31;
    int seg   = blk >> 7;          // 0..7 : b*2 + dir
    int b = seg >> 1, dir = seg & 1;
    const float* __restrict__ A  = g_pts + (size_t)((dir ? NB : 0) + b) * NS * 3;
    const float* __restrict__ Bq = g_pts + (size_t)((dir ? 0 : NB) + b) * NS * 3;
    int tid = threadIdx.x;

    float npx[4], npy[4], npz[4], mind[4];
#pragma unroll
    for (int r = 0; r < 4; r++) {
        int i = itile * 1024 + r * 256 + tid;
        float px = A[i*3+0], py = A[i*3+1], pz = A[i*3+2];
        npx[r] = -2.0f * tf32r(px);                  // exact scale of tf32 value
        npy[r] = -2.0f * tf32r(py);
        npz[r] = -2.0f * tf32r(pz);
        mind[r] = 3.4e38f;
    }

    __shared__ float4 sq[128];
    if (tid < 128) {
        int j = qt * 128 + tid;
        float qx = Bq[j*3+0], qy = Bq[j*3+1], qz = Bq[j*3+2];
        sq[tid] = make_float4(tf32r(qx), tf32r(qy), tf32r(qz),
                              qx*qx + qy*qy + qz*qz);
    }
    __syncthreads();
#pragma unroll 4
    for (int k = 0; k < 128; k++) {
        float4 q = sq[k];
#pragma unroll
        for (int r = 0; r < 4; r++) {
            float d = __fmaf_rn(q.z, npz[r], q.w);
            d = __fmaf_rn(q.y, npy[r], d);
            d = __fmaf_rn(q.x, npx[r], d);
            mind[r] = fminf(mind[r], d);
        }
    }
#pragma unroll
    for (int r = 0; r < 4; r++) {
        int i = itile * 1024 + r * 256 + tid;
        g_pmin[(seg * 32 + qt) * NS + i] = mind[r];
    }
}

// ---------------- combine partial mins + finalize (fence+counter) ----------------
__global__ void __launch_bounds__(256) k_combine(float* out)
{
    int t = blockIdx.x * 256 + threadIdx.x;   // 0..32767
    int seg = t >> 12, i = t & (NS - 1);
    int b = seg >> 1, dir = seg & 1;
    const float* __restrict__ A = g_pts + (size_t)((dir ? NB : 0) + b) * NS * 3;
    float px = A[i*3+0], py = A[i*3+1], pz = A[i*3+2];
    float pp = px*px + py*py + pz*pz;         // exact f32, as before
    const float* pm = g_pmin + seg * 32 * NS + i;
    float m = 3.4e38f;
#pragma unroll
    for (int q = 0; q < 32; q++)
        m = fminf(m, pm[q * NS]);
    __shared__ double sd[256];
    sd[threadIdx.x] = (double)(m + pp);
    __syncthreads();
    for (int off = 128; off > 0; off >>= 1) {
        if (threadIdx.x < off) sd[threadIdx.x] += sd[threadIdx.x + off];
        __syncthreads();
    }
    if (threadIdx.x == 0) {
        atomicAdd(&g_acc, sd[0]);
        __threadfence();
        unsigned done = atomicAdd(&g_cnt, 1u);
        if (done == 127u)                     // last block: all adds visible
            out[0] = (float)(g_acc * (1.0 / 16384.0));  // mean(d1)+mean(d2)
    }
}

// ---------------- launch ----------------
extern "C" void kernel_launch(void* const* d_in, const int* in_sizes, int n_in,
                              void* d_out, int out_size)
{
    const float* pv = (const float*)d_in[0];
    const void*  pf = (const void*)d_in[1];
    const float* gv = (const float*)d_in[2];
    const void*  gf = (const void*)d_in[3];

    // Partitionable (foldlike) split: key_i = threefry(key, (0, i)), both
    // outputs form the new key. key(42) = (0, 42).
    Keys keys;
    for (int b = 0; b < 4; b++) {
        unsigned kb0, kb1;
        tf2x32(0u, 42u, 0u, (unsigned)b, kb0, kb1);
        tf2x32(kb0, kb1, 0u, 0u, keys.k1[b][0], keys.k1[b][1]);
        tf2x32(kb0, kb1, 0u, 1u, keys.k2[b][0], keys.k2[b][1]);
        tf2x32(kb0, kb1, 0u, 2u, keys.k3[b][0], keys.k3[b][1]);
    }

    k_area<<<(2 * NB * NF + 255) / 256, 256>>>(pv, pf, gv, gf);
    k_argmin<<<NB * NS / 4, 128>>>(keys, pv, pf, gv, gf);
    k_chamfer<<<1024, 256>>>();
    k_combine<<<128, 256>>>((float*)d_out);
}

// round 17
// speedup vs baseline: 1.0909x; 1.0026x over previous
#include <cuda_runtime.h>

#define NB 4
#define NV 6890
#define NF 13776
#define NS 4096

struct Keys {
    unsigned k1[NB][2];
    unsigned k2[NB][2];
    unsigned k3[NB][2];
};

__device__ float2   g_invw2[NB * NF];        // (wpred, wgt) interleaved
__device__ float    g_pts [2 * NB * NS * 3];
__device__ unsigned g_dmin[8 * NS];          // ordered-key mins [seg][i]
__device__ double   g_acc;
__device__ unsigned g_cnt;
__device__ int      g_is64;
__device__ unsigned g_one = 1;               // opaque 1: forces IMAD, not IADD3

// ---------------- threefry2x32 (20 rounds), exact JAX semantics ----------------
__host__ __device__ __forceinline__ void tf2x32(unsigned k0, unsigned k1,
                                                unsigned c0, unsigned c1,
                                                unsigned &o0, unsigned &o1)
{
    unsigned ks2 = k0 ^ k1 ^ 0x1BD11BDAu;
    unsigned x0 = c0 + k0;
    unsigned x1 = c1 + k1;
#if defined(__CUDA_ARCH__)
#define TF_ROTL(x, r) __funnelshift_l((x), (x), (r))
#else
#define TF_ROTL(x, r) (((x) << (r)) | ((x) >> (32 - (r))))
#endif
#define TF_RND(r) { x0 += x1; x1 = TF_ROTL(x1, r); x1 ^= x0; }
    TF_RND(13) TF_RND(15) TF_RND(26) TF_RND(6)
    x0 += k1;  x1 += ks2 + 1u;
    TF_RND(17) TF_RND(29) TF_RND(16) TF_RND(24)
    x0 += ks2; x1 += k0 + 2u;
    TF_RND(13) TF_RND(15) TF_RND(26) TF_RND(6)
    x0 += k0;  x1 += k1 + 3u;
    TF_RND(17) TF_RND(29) TF_RND(16) TF_RND(24)
    x0 += k1;  x1 += ks2 + 4u;
    TF_RND(13) TF_RND(15) TF_RND(26) TF_RND(6)
    x0 += ks2; x1 += k0 + 5u;
#undef TF_RND
#undef TF_ROTL
    o0 = x0; o1 = x1;
}

// partitionable random_bits (32-bit): counter = (0, flat_index), out = x0 ^ x1
__host__ __device__ __forceinline__ unsigned tf_bits(unsigned k0, unsigned k1,
                                                     unsigned e)
{
    unsigned o0, o1;
    tf2x32(k0, k1, 0u, e, o0, o1);
    return o0 ^ o1;
}

// Pipe-balanced threefry for c0=0: integer adds forced onto the fma pipe as
// IMAD (mad.lo with opaque one); SHF/LOP3 stay on the alu pipe.
// Caller passes cnt = e + k1 (pre-added).
#define MADD(d, a) asm("mad.lo.u32 %0, %1, %2, %0;" : "+r"(d) : "r"(a), "r"(one))

__device__ __forceinline__ unsigned tf_fast(unsigned k0, unsigned k1, unsigned ks2,
                                            unsigned B1, unsigned B2, unsigned B3,
                                            unsigned B4, unsigned B5,
                                            unsigned cnt, unsigned one)
{
    unsigned x0 = k0;        // 0 + k0
    unsigned x1 = cnt;       // e + k1 (pre-added by caller)
#define TFR(r) { MADD(x0, x1); x1 = __funnelshift_l(x1, x1, r) ^ x0; }
    TFR(13) TFR(15) TFR(26) TFR(6)
    MADD(x0, k1);  MADD(x1, B1);
    TFR(17) TFR(29) TFR(16) TFR(24)
    MADD(x0, ks2); MADD(x1, B2);
    TFR(13) TFR(15) TFR(26) TFR(6)
    MADD(x0, k0);  MADD(x1, B3);
    TFR(17) TFR(29) TFR(16) TFR(24)
    MADD(x0, k1);  MADD(x1, B4);
    TFR(13) TFR(15) TFR(26) TFR(6)
    MADD(x0, ks2); MADD(x1, B5);
#undef TFR
    return x0 ^ x1;
}

// -------- accurate -log(u'), u' = (m==0 ? tiny : m*2^-23), ~1-2 ulp relative ----
__device__ __forceinline__ float neglog_u(unsigned m)  // m = bits >> 9
{
    float u;
    if (m == 0u) u = 1.17549435e-38f;                         // finfo(f32).tiny
    else         u = __uint_as_float(0x3f800000u | m) - 1.0f; // exact
    unsigned bi = __float_as_uint(u);
    int e = (int)(bi >> 23) - 126;                            // u = x0*2^e, x0 in [0.5,1)
    float x = __uint_as_float((bi & 0x007fffffu) | (126u << 23));
    if (x < 0.70710678f) { x = x + x; e -= 1; }               // x in [0.7071, 1.4142)
    float s = __fdiv_rn(x - 1.0f, x + 1.0f);                  // x-1 exact (Sterbenz)
    float t = s * s;
    float P = __fmaf_rn(t, __fmaf_rn(t, __fmaf_rn(t, 0.11111111f, 0.14285715f),
                                     0.2f), 0.33333334f);
    float q = s + s;
    float lnx = __fmaf_rn(q * t, P, q);                       // ln x = 2s + 2s*t*P
    float kf = (float)e;
    float r = __fmaf_rn(kf, -2.12194440e-4f, lnx);            // ln2_lo
    r = __fmaf_rn(kf, 0.693359375f, r);                       // ln2_hi
    return -r;
}

// ---------------- tf32 rounding (RNA, matches cvt.rna.tf32.f32) ----------------
__device__ __forceinline__ float tf32r(float x)
{
    unsigned b = __float_as_uint(x);
    b = (b + 0x1000u) & 0xffffe000u;
    return __uint_as_float(b);
}

// ---------------- ordered-key float<->uint (monotone), for atomicMin ----------------
__device__ __forceinline__ unsigned fkey(float f)
{
    unsigned b = __float_as_uint(f);
    return (b & 0x80000000u) ? ~b : (b | 0x80000000u);
}
__device__ __forceinline__ float fdec(unsigned k)
{
    unsigned b = (k & 0x80000000u) ? (k & 0x7fffffffu) : ~k;
    return __uint_as_float(b);
}

__device__ __forceinline__ void load_face(const void* faces, long long fe,
                                          int &i0, int &i1, int &i2, int is64)
{
    if (is64) {
        const long long* p = (const long long*)faces + fe * 3;
        i0 = (int)p[0]; i1 = (int)p[1]; i2 = (int)p[2];
    } else {
        const int* p = (const int*)faces + fe * 3;
        i0 = p[0]; i1 = p[1]; i2 = p[2];
    }
}

// ---------------- per-face inverse (area + 1e-12), fused detect + init ----------------
__global__ void k_area(const float* __restrict__ pv, const void* __restrict__ pf,
                       const float* __restrict__ gv, const void* __restrict__ gf)
{
    __shared__ int s_is64;
    if (threadIdx.x == 0) {
        const int* pf32 = (const int*)pf;
        int is64 = 1;
        for (int i = 0; i < 64; i++)
            if (pf32[2 * i + 1] != 0) { is64 = 0; break; }
        s_is64 = is64;
        if (blockIdx.x == 0) {
            g_is64 = is64;
            g_acc = 0.0;
            g_cnt = 0u;
        }
    }
    __syncthreads();
    int is64 = s_is64;
    int t = blockIdx.x * blockDim.x + threadIdx.x;
    if (t < 8 * NS) g_dmin[t] = 0xffffffffu;          // runs before k_chamfer
    if (t >= 2 * NB * NF) return;
    int type = t / (NB * NF);
    int rem  = t - type * (NB * NF);
    int b = rem / NF, f = rem - b * NF;
    const float* verts = (type ? gv : pv) + (size_t)b * NV * 3;
    int i0, i1, i2;
    load_face(type ? gf : pf, (long long)b * NF + f, i0, i1, i2, is64);
    float v0x = verts[i0*3+0], v0y = verts[i0*3+1], v0z = verts[i0*3+2];
    float ax = verts[i1*3+0] - v0x, ay = verts[i1*3+1] - v0y, az = verts[i1*3+2] - v0z;
    float bx = verts[i2*3+0] - v0x, by = verts[i2*3+1] - v0y, bz = verts[i2*3+2] - v0z;
    float cx = ay * bz - az * by;
    float cy = az * bx - ax * bz;
    float cz = ax * by - ay * bx;
    float cn = __fsqrt_rn(cx * cx + cy * cy + cz * cz);
    ((float*)g_invw2)[(b * NF + f) * 2 + type] = __fdiv_rn(1.0f, 0.5f * cn + 1e-12f);
}

// ---------------- gumbel-argmin + fused point generation ----------------
// Inner loop is the R9 configuration verbatim (best measured: 765 us).
#define PROCESS2(bits1, bits2, wva, wvb, fcur) {                                \
    unsigned m1 = (bits1) >> 9, m2 = (bits2) >> 9;                              \
    float yl1 = 2.0f - __uint_as_float(0x3f800000u | m1);                       \
    float yl2 = 2.0f - __uint_as_float(0x3f800000u | m2);                       \
    float c0a = __fmul_rn(yl1, (wva).x), c1a = __fmul_rn(yl1, (wva).y);         \
    float c0b = __fmul_rn(yl2, (wvb).x), c1b = __fmul_rn(yl2, (wvb).y);         \
    if (fminf(c0a, c0b) < bb0f || fminf(c1a, c1b) < bb1f) {                     \
        float lg1 = neglog_u(m1);                                               \
        float lg2 = neglog_u(m2);                                               \
        float t0 = __fmul_rn(lg1, (wva).x);                                     \
        if (t0 < bb0f) { bb0f = t0; bf0 = (fcur); }                             \
        float t1 = __fmul_rn(lg1, (wva).y);                                     \
        if (t1 < bb1f) { bb1f = t1; bf1 = (fcur); }                             \
        float t2 = __fmul_rn(lg2, (wvb).x);                                     \
        if (t2 < bb0f) { bb0f = t2; bf0 = (fcur) + 32; }                        \
        float t3 = __fmul_rn(lg2, (wvb).y);                                     \
        if (t3 < bb1f) { bb1f = t3; bf1 = (fcur) + 32; }                        \
    } }

__global__ void __launch_bounds__(128, 14) k_argmin(
    Keys keys,
    const float* __restrict__ pv, const void* __restrict__ pf,
    const float* __restrict__ gv, const void* __restrict__ gf)
{
    unsigned one = g_one;
    int gw   = blockIdx.x * 4 + (threadIdx.x >> 5);  // global warp = row id
    int lane = threadIdx.x & 31;
    int b = gw >> 12;                                // 4096 rows per batch
    int i = gw & (NS - 1);
    unsigned k0 = keys.k1[b][0], k1 = keys.k1[b][1];
    unsigned ks2 = k0 ^ k1 ^ 0x1BD11BDAu;
    unsigned B1 = ks2 + 1u, B2 = k0 + 2u, B3 = k1 + 3u, B4 = ks2 + 4u, B5 = k0 + 5u;
    const float2* __restrict__ w2 = g_invw2 + b * NF;
    float bb0f = 3.402823466e38f, bb1f = 3.402823466e38f;
    int bf0 = NF, bf1 = NF;
    unsigned eoff = (unsigned)i * (unsigned)NF + k1;

    int f1 = lane;
    unsigned cnt1 = eoff + (unsigned)lane;

    // 215 iterations x 2 chains (215 x 64 = 13760), tail 16
    for (int t = 0; t < 215; t++) {
        unsigned bits1 = tf_fast(k0, k1, ks2, B1, B2, B3, B4, B5, cnt1,       one);
        unsigned bits2 = tf_fast(k0, k1, ks2, B1, B2, B3, B4, B5, cnt1 + 32u, one);
        float2 wa = __ldg(w2 + f1);
        float2 wb = __ldg(w2 + f1 + 32);
        PROCESS2(bits1, bits2, wa, wb, f1)
        f1 += 64;
        MADD(cnt1, 64u);
    }
    if (lane < 16) {                                  // f in [13760, 13776)
        unsigned bits = tf_fast(k0, k1, ks2, B1, B2, B3, B4, B5, cnt1, one);
        float2 wt = __ldg(w2 + f1);
        unsigned m = bits >> 9;
        float yl = 2.0f - __uint_as_float(0x3f800000u | m);
        float c0 = __fmul_rn(yl, wt.x), c1 = __fmul_rn(yl, wt.y);
        if (c0 < bb0f || c1 < bb1f) {
            float lg = neglog_u(m);
            float t0 = __fmul_rn(lg, wt.x);
            if (t0 < bb0f) { bb0f = t0; bf0 = f1; }
            float t1 = __fmul_rn(lg, wt.y);
            if (t1 < bb1f) { bb1f = t1; bf1 = f1; }
        }
    }

#pragma unroll
    for (int off = 16; off > 0; off >>= 1) {
        float ob; int of;
        ob = __shfl_down_sync(0xffffffffu, bb0f, off);
        of = __shfl_down_sync(0xffffffffu, bf0, off);
        if (ob < bb0f || (ob == bb0f && of < bf0)) { bb0f = ob; bf0 = of; }
        ob = __shfl_down_sync(0xffffffffu, bb1f, off);
        of = __shfl_down_sync(0xffffffffu, bf1, off);
        if (ob < bb1f || (ob == bb1f && of < bf1)) { bb1f = ob; bf1 = of; }
    }

    // ---- fused point generation (once per row; lanes 0/1 handle pred/gt) ----
    int wf0 = __shfl_sync(0xffffffffu, bf0, 0);
    int wf1 = __shfl_sync(0xffffffffu, bf1, 0);
    unsigned myb = 0;
    if (lane < 2) {
        // lane 0: u-bits (key2); lane 1: w-bits (key3)
        unsigned kk0 = lane ? keys.k3[b][0] : keys.k2[b][0];
        unsigned kk1 = lane ? keys.k3[b][1] : keys.k2[b][1];
        myb = tf_bits(kk0, kk1, (unsigned)i);
    }
    unsigned bu = __shfl_sync(0xffffffffu, myb, 0);
    unsigned bw = __shfl_sync(0xffffffffu, myb, 1);
    if (lane < 2) {
        int is64 = g_is64;
        int type = lane;
        int f = type ? wf1 : wf0;
        float u = __uint_as_float(0x3f800000u | (bu >> 9)) - 1.0f;
        float w = __uint_as_float(0x3f800000u | (bw >> 9)) - 1.0f;
        float r = __fsqrt_rn(u);
        float a0 = 1.0f - r;
        float a1 = __fmul_rn(r, 1.0f - w);
        float a2 = __fmul_rn(r, w);
        const float* verts = (type ? gv : pv) + (size_t)b * NV * 3;
        int i0, i1, i2;
        load_face(type ? gf : pf, (long long)b * NF + f, i0, i1, i2, is64);
        float* dst = g_pts + ((size_t)(type * NB + b) * NS + i) * 3;
#pragma unroll
        for (int c = 0; c < 3; c++)
            dst[c] = a0 * verts[i0*3+c] + a1 * verts[i1*3+c] + a2 * verts[i2*3+c];
    }
}

// ---------------- brute-force two-way chamfer, TF32-emulated dot ----------------
// pp hoisted (re-added in k_combine); -2 folded into tf32-rounded i-point.
// Partial mins merged via atomicMin on a monotone uint key (exact min; order-free).
__global__ void __launch_bounds__(256) k_chamfer()
{
    int blk   = blockIdx.x;        // 1024
    int itile = blk & 3;
    int qt    = (blk >> 2) & 31;
    int seg   = blk >> 7;          // 0..7 : b*2 + dir
    int b = seg >> 1, dir = seg & 1;
    const float* __restrict__ A  = g_pts + (size_t)((dir ? NB : 0) + b) * NS * 3;
    const float* __restrict__ Bq = g_pts + (size_t)((dir ? 0 : NB) + b) * NS * 3;
    int tid = threadIdx.x;

    float npx[4], npy[4], npz[4], mind[4];
#pragma unroll
    for (int r = 0; r < 4; r++) {
        int i = itile * 1024 + r * 256 + tid;
        float px = A[i*3+0], py = A[i*3+1], pz = A[i*3+2];
        npx[r] = -2.0f * tf32r(px);                  // exact scale of tf32 value
        npy[r] = -2.0f * tf32r(py);
        npz[r] = -2.0f * tf32r(pz);
        mind[r] = 3.4e38f;
    }

    __shared__ float4 sq[128];
    if (tid < 128) {
        int j = qt * 128 + tid;
        float qx = Bq[j*3+0], qy = Bq[j*3+1], qz = Bq[j*3+2];
        sq[tid] = make_float4(tf32r(qx), tf32r(qy), tf32r(qz),
                              qx*qx + qy*qy + qz*qz);
    }
    __syncthreads();
#pragma unroll 4
    for (int k = 0; k < 128; k++) {
        float4 q = sq[k];
#pragma unroll
        for (int r = 0; r < 4; r++) {
            float d = __fmaf_rn(q.z, npz[r], q.w);
            d = __fmaf_rn(q.y, npy[r], d);
            d = __fmaf_rn(q.x, npx[r], d);
            mind[r] = fminf(mind[r], d);
        }
    }
#pragma unroll
    for (int r = 0; r < 4; r++) {
        int i = itile * 1024 + r * 256 + tid;
        atomicMin(&g_dmin[seg * NS + i], fkey(mind[r]));
    }
}

// ---------------- combine mins + finalize (fence+counter) ----------------
__global__ void __launch_bounds__(256) k_combine(float* out)
{
    int t = blockIdx.x * 256 + threadIdx.x;   // 0..32767
    int seg = t >> 12, i = t & (NS - 1);
    int b = seg >> 1, dir = seg & 1;
    const float* __restrict__ A = g_pts + (size_t)((dir ? NB : 0) + b) * NS * 3;
    float px = A[i*3+0], py = A[i*3+1], pz = A[i*3+2];
    float pp = px*px + py*py + pz*pz;         // exact f32, as before
    float m = fdec(g_dmin[t]);
    __shared__ double sd[256];
    sd[threadIdx.x] = (double)(m + pp);
    __syncthreads();
    for (int off = 128; off > 0; off >>= 1) {
        if (threadIdx.x < off) sd[threadIdx.x] += sd[threadIdx.x + off];
        __syncthreads();
    }
    if (threadIdx.x == 0) {
        atomicAdd(&g_acc, sd[0]);
        __threadfence();
        unsigned done = atomicAdd(&g_cnt, 1u);
        if (done == 127u)                     // last block: all adds visible
            out[0] = (float)(g_acc * (1.0 / 16384.0));  // mean(d1)+mean(d2)
    }
}

// ---------------- launch ----------------
extern "C" void kernel_launch(void* const* d_in, const int* in_sizes, int n_in,
                              void* d_out, int out_size)
{
    const float* pv = (const float*)d_in[0];
    const void*  pf = (const void*)d_in[1];
    const float* gv = (const float*)d_in[2];
    const void*  gf = (const void*)d_in[3];

    // Partitionable (foldlike) split: key_i = threefry(key, (0, i)), both
    // outputs form the new key. key(42) = (0, 42).
    Keys keys;
    for (int b = 0; b < 4; b++) {
        unsigned kb0, kb1;
        tf2x32(0u, 42u, 0u, (unsigned)b, kb0, kb1);
        tf2x32(kb0, kb1, 0u, 0u, keys.k1[b][0], keys.k1[b][1]);
        tf2x32(kb0, kb1, 0u, 1u, keys.k2[b][0], keys.k2[b][1]);
        tf2x32(kb0, kb1, 0u, 2u, keys.k3[b][0], keys.k3[b][1]);
    }

    k_area<<<(2 * NB * NF + 255) / 256, 256>>>(pv, pf, gv, gf);
    k_argmin<<<NB * NS / 4, 128>>>(keys, pv, pf, gv, gf);
    k_chamfer<<<1024, 256>>>();
    k_combine<<<128, 256>>>((float*)d_out);
}